// round 7
// baseline (speedup 1.0000x reference)
#include <cuda_runtime.h>
#include <cuda_fp16.h>
#include <math.h>
#include <stdint.h>

// ---------------------------------------------------------------------------
// Problem constants
// ---------------------------------------------------------------------------
namespace {
constexpr int B = 4;
constexpr int T = 2048;
constexpr int D = 1024;      // D_IN == D_OUT
constexpr int MPROJ = B * T; // 8192

// Scratch (allocation-free: __device__ globals)
__device__ __half g_x [(size_t)MPROJ * D];   // 16 MB  fp16 input
__device__ __half g_wt[3][(size_t)D * D];    // 6 MB   fp16 W^T (n-major)
__device__ __half g_q [(size_t)B * T * D];   // 16 MB
__device__ __half g_k [(size_t)B * T * D];   // 16 MB
__device__ __half g_v [(size_t)B * T * D];   // 16 MB
__device__ __half g_vt[(size_t)B * D * T];   // 16 MB  V^T per batch
__device__ float  g_s [(size_t)B * T * T];   // 64 MB  raw scores (fp32)
__device__ __half g_ph[(size_t)B * T * T];   // 32 MB  probs (fp16)
} // namespace

// ---------------------------------------------------------------------------
// Helpers
// ---------------------------------------------------------------------------
__device__ __forceinline__ uint32_t smem_u32(const void* p) {
    uint32_t a;
    asm("{ .reg .u64 t; cvta.to.shared.u64 t, %1; cvt.u32.u64 %0, t; }"
        : "=r"(a) : "l"(p));
    return a;
}

__device__ __forceinline__ void cp16(uint32_t dst, const void* src) {
    asm volatile("cp.async.cg.shared.global [%0], [%1], 16;"
                 :: "r"(dst), "l"(src) : "memory");
}
#define CP_COMMIT() asm volatile("cp.async.commit_group;" ::: "memory")
#define CP_WAIT(N)  asm volatile("cp.async.wait_group %0;" :: "n"(N) : "memory")

__device__ __forceinline__ void ldsm4(uint32_t& r0, uint32_t& r1,
                                      uint32_t& r2, uint32_t& r3,
                                      uint32_t addr) {
    asm volatile("ldmatrix.sync.aligned.m8n8.x4.shared.b16 {%0,%1,%2,%3}, [%4];"
                 : "=r"(r0), "=r"(r1), "=r"(r2), "=r"(r3) : "r"(addr));
}

__device__ __forceinline__ void mma_f16(float c[4], const uint32_t a[4],
                                        const uint32_t b[2]) {
    asm volatile(
        "mma.sync.aligned.m16n8k16.row.col.f32.f16.f16.f32 "
        "{%0,%1,%2,%3}, {%4,%5,%6,%7}, {%8,%9}, {%0,%1,%2,%3};"
        : "+f"(c[0]), "+f"(c[1]), "+f"(c[2]), "+f"(c[3])
        : "r"(a[0]), "r"(a[1]), "r"(a[2]), "r"(a[3]), "r"(b[0]), "r"(b[1]));
}

// ---------------------------------------------------------------------------
// fp16 mma.sync GEMM core ("NT": both operands K-major).
//   C[m,n] += A[m,k] * Bp[n,k]
// CTA tile 256x128, BK=32 halves, 256 threads (8 warps, 4x2 grid),
// warp tile 64x64. ldmatrix.x4 fragment loads from XOR-swizzled smem
// (16-word rows, phys group = g ^ (((row>>1)&3)<<2)); conflict-free for the
// 16B cp.async stores and all LDSM phases. 4-stage cp.async pipeline.
// Stage = A(16KB) + B(8KB) = 24 KB; 4 stages = 96 KB dynamic smem. 1 CTA/SM.
// EPI: 0 = fp32 float2 stores, 1 = fp16 half2 stores.
// ---------------------------------------------------------------------------
constexpr int STAGES = 4;
constexpr int STAGE_WORDS = 6144;  // 24 KB / 4
constexpr int SMEM_BYTES = STAGES * STAGE_WORDS * 4; // 98304

template <int EPI>
__device__ __forceinline__ void hgemm(const __half* __restrict__ A,
                                      const __half* __restrict__ Bp,
                                      void* __restrict__ Cv,
                                      int lda, int ldb, int ldc,
                                      int bm, int bn, int nChunks) {
    extern __shared__ float sm[];
    const uint32_t smem_base = smem_u32(sm);

    const int tid = threadIdx.x;
    const int lane = tid & 31;
    const int wid = tid >> 5;
    const int wr = wid & 3;      // 0..3  (64-row slab)
    const int wc = wid >> 2;     // 0..1  (64-col slab)
    const int gid = lane >> 2;   // 0..7
    const int tig = lane & 3;    // 0..3

    // ldmatrix lane roles (x4 tile order: see fragment mapping in comments)
    const int a_row_off = ((lane >> 3) & 1) * 8 + (lane & 7); // within m16
    const int a_kg = lane >> 4;                                // 0..1
    const int b_row_off = (lane >> 4) * 8 + (lane & 7);        // within n16
    const int b_kg = (lane >> 3) & 1;                          // 0..1

    auto issue = [&](int chunk, int buf) {
        const int k0 = chunk * 32;
        const uint32_t sA = smem_base + (uint32_t)buf * (STAGE_WORDS * 4);
        const uint32_t sB = sA + 4096 * 4;
#pragma unroll
        for (int l = 0; l < 4; l++) {               // A: 256 rows x 32 halves
            const int idx = tid + l * 256;
            const int m = idx >> 2, c = idx & 3;
            const uint32_t sw = ((m >> 1) & 3) << 2;
            cp16(sA + (uint32_t)(m * 16 + ((4 * c) ^ sw)) * 4,
                 A + (size_t)(bm + m) * lda + k0 + 8 * c);
        }
#pragma unroll
        for (int l = 0; l < 2; l++) {               // B: 128 rows x 32 halves
            const int idx = tid + l * 256;
            const int n = idx >> 2, c = idx & 3;
            const uint32_t sw = ((n >> 1) & 3) << 2;
            cp16(sB + (uint32_t)(n * 16 + ((4 * c) ^ sw)) * 4,
                 Bp + (size_t)(bn + n) * ldb + k0 + 8 * c);
        }
    };

    float acc[4][8][4];
#pragma unroll
    for (int i = 0; i < 4; i++)
#pragma unroll
        for (int j = 0; j < 8; j++)
#pragma unroll
            for (int e = 0; e < 4; e++) acc[i][j][e] = 0.0f;

    // Per-lane invariant pieces of fragment addresses
    uint32_t aw[4], bw[4]; // row*16 and swizzle per tile-row
#pragma unroll
    for (int i = 0; i < 4; i++) {
        const int row = wr * 64 + i * 16 + a_row_off;
        aw[i] = (uint32_t)(row * 16) | (((row >> 1) & 3) << 2) << 16;
    }
#pragma unroll
    for (int jp = 0; jp < 4; jp++) {
        const int row = wc * 64 + jp * 16 + b_row_off;
        bw[jp] = (uint32_t)(row * 16) | (((row >> 1) & 3) << 2) << 16;
    }

    // Prologue (nChunks >= 8 always)
#pragma unroll
    for (int s = 0; s < STAGES - 1; s++) {
        issue(s, s);
        CP_COMMIT();
    }

    int buf = 0;
    for (int t = 0; t < nChunks; t++) {
        CP_WAIT(STAGES - 2);
        __syncthreads();

        const uint32_t sa = smem_base + (uint32_t)buf * (STAGE_WORDS * 4);
        const uint32_t sb = sa + 4096 * 4;

        if (t + STAGES - 1 < nChunks) {
            int pbuf = buf + STAGES - 1;
            if (pbuf >= STAGES) pbuf -= STAGES;
            issue(t + STAGES - 1, pbuf);
        }
        CP_COMMIT();

#pragma unroll
        for (int s = 0; s < 2; s++) { // two K=16 steps per 32-half chunk
            const uint32_t w0 = 8 * s;
            uint32_t af[4][4];
#pragma unroll
            for (int i = 0; i < 4; i++) {
                const uint32_t g = (w0 + 4 * a_kg) ^ (aw[i] >> 16);
                ldsm4(af[i][0], af[i][1], af[i][2], af[i][3],
                      sa + (((aw[i] & 0xffffu) + g) << 2));
            }
            uint32_t bf[8][2];
#pragma unroll
            for (int jp = 0; jp < 4; jp++) {
                const uint32_t g = (w0 + 4 * b_kg) ^ (bw[jp] >> 16);
                ldsm4(bf[2 * jp][0], bf[2 * jp][1], bf[2 * jp + 1][0],
                      bf[2 * jp + 1][1],
                      sb + (((bw[jp] & 0xffffu) + g) << 2));
            }
#pragma unroll
            for (int i = 0; i < 4; i++)
#pragma unroll
                for (int j = 0; j < 8; j++) mma_f16(acc[i][j], af[i], bf[j]);
        }
        if (++buf == STAGES) buf = 0;
    }

    // Epilogue
#pragma unroll
    for (int i = 0; i < 4; i++) {
        const int m = bm + wr * 64 + i * 16 + gid;
#pragma unroll
        for (int j = 0; j < 8; j++) {
            const int col = bn + wc * 64 + j * 8 + 2 * tig;
            if (EPI == 1) {
                __half* Ch = (__half*)Cv;
                *reinterpret_cast<__half2*>(Ch + (size_t)m * ldc + col) =
                    __floats2half2_rn(acc[i][j][0], acc[i][j][1]);
                *reinterpret_cast<__half2*>(Ch + (size_t)(m + 8) * ldc + col) =
                    __floats2half2_rn(acc[i][j][2], acc[i][j][3]);
            } else {
                float* Cf = (float*)Cv;
                *reinterpret_cast<float2*>(Cf + (size_t)m * ldc + col) =
                    make_float2(acc[i][j][0], acc[i][j][1]);
                *reinterpret_cast<float2*>(Cf + (size_t)(m + 8) * ldc + col) =
                    make_float2(acc[i][j][2], acc[i][j][3]);
            }
        }
    }
}

// ---------------------------------------------------------------------------
// Kernel 0a: X fp32 -> fp16
// ---------------------------------------------------------------------------
__global__ __launch_bounds__(256) void cvtx_kernel(const float4* __restrict__ src,
                                                   int n4) {
    uint2* dst = reinterpret_cast<uint2*>(g_x);
    const int stride = gridDim.x * blockDim.x;
    for (int i = blockIdx.x * blockDim.x + threadIdx.x; i < n4; i += stride) {
        const float4 v = src[i];
        __half2 h0 = __floats2half2_rn(v.x, v.y);
        __half2 h1 = __floats2half2_rn(v.z, v.w);
        uint2 u;
        u.x = *reinterpret_cast<uint32_t*>(&h0);
        u.y = *reinterpret_cast<uint32_t*>(&h1);
        dst[i] = u;
    }
}

// ---------------------------------------------------------------------------
// Kernel 0b: W fp32 [k][n] -> fp16 W^T [n][k], 32x32 smem tiles, z = weight.
// ---------------------------------------------------------------------------
__global__ __launch_bounds__(256) void wt_kernel(const float* __restrict__ Wq,
                                                 const float* __restrict__ Wk,
                                                 const float* __restrict__ Wv) {
    __shared__ float tile[32][33];
    const float* W = (blockIdx.z == 0) ? Wq : (blockIdx.z == 1) ? Wk : Wv;
    __half* Wt = g_wt[blockIdx.z];
    const int n0 = blockIdx.x * 32, k0 = blockIdx.y * 32;
    const int c = threadIdx.x & 31, r8 = threadIdx.x >> 5;
#pragma unroll
    for (int r = r8; r < 32; r += 8)
        tile[r][c] = W[(size_t)(k0 + r) * D + n0 + c];
    __syncthreads();
#pragma unroll
    for (int r = r8; r < 32; r += 8)
        Wt[(size_t)(n0 + r) * D + k0 + c] = __float2half_rn(tile[c][r]);
}

// ---------------------------------------------------------------------------
// Kernel 0c: V fp16 [b][t][d] -> V^T [b][d][t]
// ---------------------------------------------------------------------------
__global__ __launch_bounds__(256) void vt_kernel() {
    __shared__ __half tile[32][33];
    const int b = blockIdx.z;
    const __half* V = g_v + (size_t)b * T * D;
    __half* Vt = g_vt + (size_t)b * D * T;
    const int t0 = blockIdx.x * 32, d0 = blockIdx.y * 32;
    const int c = threadIdx.x & 31, r8 = threadIdx.x >> 5;
#pragma unroll
    for (int r = r8; r < 32; r += 8)
        tile[r][c] = V[(size_t)(t0 + r) * D + d0 + c];
    __syncthreads();
#pragma unroll
    for (int r = r8; r < 32; r += 8)
        Vt[(size_t)(d0 + r) * T + t0 + c] = tile[c][r];
}

// ---------------------------------------------------------------------------
// Kernel 1: fused QKV projection: g_x @ g_wt[z]^T -> fp16 Q/K/V.
// grid: (D/128=8, MPROJ/256=32, 3)
// ---------------------------------------------------------------------------
__global__ __launch_bounds__(256, 1) void proj_kernel() {
    __half* C = (blockIdx.z == 0) ? g_q : (blockIdx.z == 1) ? g_k : g_v;
    hgemm<1>(g_x, g_wt[blockIdx.z], C, D, D, D, blockIdx.y * 256,
             blockIdx.x * 128, D / 32);
}

// ---------------------------------------------------------------------------
// Kernel 2: scores S[b] = Q[b] @ K[b]^T (fp32 out). M tile 256 x N tile 128:
// skip tiles fully above the diagonal (kn*128 > qm*256+255).
// ---------------------------------------------------------------------------
__global__ __launch_bounds__(256, 1) void scores_kernel() {
    const int qm = blockIdx.y;
    const int kn = blockIdx.x;
    if (kn > 2 * qm + 1) return;
    const int b = blockIdx.z;
    hgemm<0>(g_q + (size_t)b * T * D, g_k + (size_t)b * T * D,
             g_s + (size_t)b * T * T, D, D, T, qm * 256, kn * 128, D / 32);
}

// ---------------------------------------------------------------------------
// Kernel 3: row softmax: g_s fp32 -> g_ph fp16, padded with zeros to the end
// of the 256-aligned diagonal block (covers every PV read).
// ---------------------------------------------------------------------------
__global__ __launch_bounds__(256) void softmax_kernel() {
    __shared__ float buf[T];
    __shared__ float redm[8];
    __shared__ float reds[8];

    const int row = blockIdx.x;
    const int b = row >> 11;
    const int q = row & 2047;
    const float* S = g_s + (size_t)b * T * T + (size_t)q * T;
    __half2* P2 = reinterpret_cast<__half2*>(g_ph + (size_t)b * T * T +
                                             (size_t)q * T);

    const int tid = threadIdx.x;
    const int lane = tid & 31;
    const int wid = tid >> 5;
    const int n = q + 1;
    const int nup = (((q >> 8) + 1) << 8); // round_up(n, 256)
    const int nw4 = (n + 3) >> 2;
    const float scale = 0.03125f; // 1/sqrt(1024)
    const float4* S4 = reinterpret_cast<const float4*>(S);

    float m = -1e30f;
    for (int j = tid; j < nw4; j += 256) {
        const float4 v = S4[j];
        const int k = 4 * j;
        if (k + 0 < n) m = fmaxf(m, v.x);
        if (k + 1 < n) m = fmaxf(m, v.y);
        if (k + 2 < n) m = fmaxf(m, v.z);
        if (k + 3 < n) m = fmaxf(m, v.w);
    }
#pragma unroll
    for (int s = 16; s > 0; s >>= 1)
        m = fmaxf(m, __shfl_xor_sync(0xffffffffu, m, s));
    if (lane == 0) redm[wid] = m;
    __syncthreads();
    float mAll = redm[0];
#pragma unroll
    for (int w = 1; w < 8; w++) mAll = fmaxf(mAll, redm[w]);
    const float mS = mAll * scale;

    float lsum = 0.0f;
    float4* buf4 = reinterpret_cast<float4*>(buf);
    for (int j = tid; j < nw4; j += 256) {
        const float4 v = S4[j];
        const int k = 4 * j;
        float4 e;
        e.x = (k + 0 < n) ? __expf(fmaf(v.x, scale, -mS)) : 0.0f;
        e.y = (k + 1 < n) ? __expf(fmaf(v.y, scale, -mS)) : 0.0f;
        e.z = (k + 2 < n) ? __expf(fmaf(v.z, scale, -mS)) : 0.0f;
        e.w = (k + 3 < n) ? __expf(fmaf(v.w, scale, -mS)) : 0.0f;
        buf4[j] = e;
        lsum += e.x + e.y + e.z + e.w;
    }
#pragma unroll
    for (int s = 16; s > 0; s >>= 1)
        lsum += __shfl_xor_sync(0xffffffffu, lsum, s);
    if (lane == 0) reds[wid] = lsum;
    __syncthreads();
    float tot = 0.0f;
#pragma unroll
    for (int w = 0; w < 8; w++) tot += reds[w];
    const float inv = 1.0f / tot;

    for (int j = tid; j < (nup >> 1); j += 256) {
        const int k = 2 * j;
        const float v0 = (k + 0 < n) ? buf[k + 0] * inv : 0.0f;
        const float v1 = (k + 1 < n) ? buf[k + 1] * inv : 0.0f;
        P2[j] = __floats2half2_rn(v0, v1);
    }
}

// ---------------------------------------------------------------------------
// Kernel 4: O[b] = P[b] @ V[b] = P @ (V^T)^T, k-truncated at the diagonal.
// M tile 256; longest q-blocks launched first.
// ---------------------------------------------------------------------------
__global__ __launch_bounds__(256, 1) void pv_kernel(float* __restrict__ O) {
    const int b = blockIdx.z;
    const int qm = (gridDim.y - 1) - blockIdx.y;
    hgemm<0>(g_ph + (size_t)b * T * T, g_vt + (size_t)b * D * T,
             O + (size_t)b * T * D, T, T, D, qm * 256, blockIdx.x * 128,
             (qm + 1) * 8);
}

// ---------------------------------------------------------------------------
extern "C" void kernel_launch(void* const* d_in, const int* in_sizes, int n_in,
                              void* d_out, int out_size) {
    (void)in_sizes; (void)n_in; (void)out_size;
    const float4* X  = (const float4*)d_in[0];
    const float*  Wq = (const float*)d_in[1];
    const float*  Wk = (const float*)d_in[2];
    const float*  Wv = (const float*)d_in[3];
    float* O = (float*)d_out;

    cudaFuncSetAttribute(proj_kernel,
                         cudaFuncAttributeMaxDynamicSharedMemorySize,
                         SMEM_BYTES);
    cudaFuncSetAttribute(scores_kernel,
                         cudaFuncAttributeMaxDynamicSharedMemorySize,
                         SMEM_BYTES);
    cudaFuncSetAttribute(pv_kernel,
                         cudaFuncAttributeMaxDynamicSharedMemorySize,
                         SMEM_BYTES);

    cvtx_kernel<<<1024, 256>>>(X, MPROJ * D / 4);
    wt_kernel<<<dim3(D / 32, D / 32, 3), 256>>>(Wq, Wk, Wv);

    proj_kernel<<<dim3(D / 128, MPROJ / 256, 3), 256, SMEM_BYTES>>>();
    vt_kernel<<<dim3(T / 32, D / 32, B), 256>>>();
    scores_kernel<<<dim3(T / 128, T / 256, B), 256, SMEM_BYTES>>>();
    softmax_kernel<<<dim3(B * T), 256>>>();
    pv_kernel<<<dim3(D / 128, T / 256, B), 256, SMEM_BYTES>>>(O);
}

// round 8
// speedup vs baseline: 1.1904x; 1.1904x over previous
#include <cuda_runtime.h>
#include <cuda_fp16.h>
#include <math.h>
#include <stdint.h>

// ---------------------------------------------------------------------------
// Problem constants
// ---------------------------------------------------------------------------
namespace {
constexpr int B = 4;
constexpr int T = 2048;
constexpr int D = 1024;      // D_IN == D_OUT
constexpr int MPROJ = B * T; // 8192

// Scratch (allocation-free: __device__ globals)
__device__ __half g_x [(size_t)MPROJ * D];   // 16 MB  fp16 input
__device__ __half g_wt[3][(size_t)D * D];    // 6 MB   fp16 W^T (n-major)
__device__ __half g_q [(size_t)B * T * D];   // 16 MB
__device__ __half g_k [(size_t)B * T * D];   // 16 MB
__device__ __half g_v [(size_t)B * T * D];   // 16 MB
__device__ __half g_vt[(size_t)B * D * T];   // 16 MB  V^T per batch
__device__ __half g_ph[(size_t)B * T * T];   // 32 MB  unnormalized probs fp16
__device__ float  g_rinv[(size_t)B * T];     // 32 KB  1/rowsum
} // namespace

// ---------------------------------------------------------------------------
// Helpers
// ---------------------------------------------------------------------------
__device__ __forceinline__ uint32_t smem_u32(const void* p) {
    uint32_t a;
    asm("{ .reg .u64 t; cvta.to.shared.u64 t, %1; cvt.u32.u64 %0, t; }"
        : "=r"(a) : "l"(p));
    return a;
}

__device__ __forceinline__ void cp16(uint32_t dst, const void* src) {
    asm volatile("cp.async.cg.shared.global [%0], [%1], 16;"
                 :: "r"(dst), "l"(src) : "memory");
}
#define CP_COMMIT() asm volatile("cp.async.commit_group;" ::: "memory")
#define CP_WAIT(N)  asm volatile("cp.async.wait_group %0;" :: "n"(N) : "memory")

__device__ __forceinline__ void ldsm4(uint32_t& r0, uint32_t& r1,
                                      uint32_t& r2, uint32_t& r3,
                                      uint32_t addr) {
    asm volatile("ldmatrix.sync.aligned.m8n8.x4.shared.b16 {%0,%1,%2,%3}, [%4];"
                 : "=r"(r0), "=r"(r1), "=r"(r2), "=r"(r3) : "r"(addr));
}

__device__ __forceinline__ void mma_f16(float c[4], const uint32_t a[4],
                                        const uint32_t b[2]) {
    asm volatile(
        "mma.sync.aligned.m16n8k16.row.col.f32.f16.f16.f32 "
        "{%0,%1,%2,%3}, {%4,%5,%6,%7}, {%8,%9}, {%0,%1,%2,%3};"
        : "+f"(c[0]), "+f"(c[1]), "+f"(c[2]), "+f"(c[3])
        : "r"(a[0]), "r"(a[1]), "r"(a[2]), "r"(a[3]), "r"(b[0]), "r"(b[1]));
}

// ---------------------------------------------------------------------------
// fp16 mma.sync GEMM core ("NT": both operands K-major).
//   C[m,n] += A[m,k] * Bp[n,k]
// CTA tile 128x128, BK=32 halves, 256 threads (8 warps, 2x4 grid),
// warp tile 64x32. ldmatrix.x4 fragment loads from XOR-swizzled smem
// (16-word rows, phys group = g ^ (((row>>1)&3)<<2)).
// 3-stage cp.async pipeline; stage = 16 KB; 48 KB smem -> 2 CTAs/SM.
// EPI: 1 = plain fp16 stores (proj)
//      2 = exp(s*SCALE - EXPC) with causal mask, fp16 stores (scores)
//      3 = fp32 stores scaled by aux[m] (pv; aux = per-row 1/sum)
// ---------------------------------------------------------------------------
constexpr int STAGES = 3;
constexpr int STAGE_WORDS = 4096;  // 16 KB / 4
constexpr int SMEM_BYTES = STAGES * STAGE_WORDS * 4; // 49152
constexpr float SCALE = 0.03125f;  // 1/sqrt(1024)
constexpr float EXPC = 5.0f;       // fixed exp offset (cancels in normalize)

template <int EPI>
__device__ __forceinline__ void hgemm(const __half* __restrict__ A,
                                      const __half* __restrict__ Bp,
                                      void* __restrict__ Cv,
                                      const float* __restrict__ aux,
                                      int lda, int ldb, int ldc,
                                      int bm, int bn, int nChunks) {
    extern __shared__ float sm[];
    const uint32_t smem_base = smem_u32(sm);

    const int tid = threadIdx.x;
    const int lane = tid & 31;
    const int wid = tid >> 5;
    const int wr = wid >> 2;     // 0..1  (64-row slab)
    const int wc = wid & 3;      // 0..3  (32-col slab)
    const int gid = lane >> 2;   // 0..7
    const int tig = lane & 3;    // 0..3

    // ldmatrix lane roles (mapping validated in R6)
    const int a_row_off = ((lane >> 3) & 1) * 8 + (lane & 7);
    const int a_kg = lane >> 4;
    const int b_row_off = (lane >> 4) * 8 + (lane & 7);
    const int b_kg = (lane >> 3) & 1;

    auto issue = [&](int chunk, int buf) {
        const int k0 = chunk * 32;
        const uint32_t sA = smem_base + (uint32_t)buf * (STAGE_WORDS * 4);
        const uint32_t sB = sA + 2048 * 4;
#pragma unroll
        for (int l = 0; l < 2; l++) {               // A: 128 rows x 32 halves
            const int idx = tid + l * 256;
            const int m = idx >> 2, c = idx & 3;
            const uint32_t sw = ((m >> 1) & 3) << 2;
            cp16(sA + (uint32_t)(m * 16 + ((4 * c) ^ sw)) * 4,
                 A + (size_t)(bm + m) * lda + k0 + 8 * c);
        }
#pragma unroll
        for (int l = 0; l < 2; l++) {               // B: 128 rows x 32 halves
            const int idx = tid + l * 256;
            const int n = idx >> 2, c = idx & 3;
            const uint32_t sw = ((n >> 1) & 3) << 2;
            cp16(sB + (uint32_t)(n * 16 + ((4 * c) ^ sw)) * 4,
                 Bp + (size_t)(bn + n) * ldb + k0 + 8 * c);
        }
    };

    float acc[4][4][4];
#pragma unroll
    for (int i = 0; i < 4; i++)
#pragma unroll
        for (int j = 0; j < 4; j++)
#pragma unroll
            for (int e = 0; e < 4; e++) acc[i][j][e] = 0.0f;

    // Per-lane invariant fragment address pieces: low 16 = row*16, hi = swizzle
    uint32_t aw[4], bw[2];
#pragma unroll
    for (int i = 0; i < 4; i++) {
        const int row = wr * 64 + i * 16 + a_row_off;
        aw[i] = (uint32_t)(row * 16) | (((row >> 1) & 3) << 2) << 16;
    }
#pragma unroll
    for (int jp = 0; jp < 2; jp++) {
        const int row = wc * 32 + jp * 16 + b_row_off;
        bw[jp] = (uint32_t)(row * 16) | (((row >> 1) & 3) << 2) << 16;
    }

    // Prologue (nChunks >= 4 always)
#pragma unroll
    for (int s = 0; s < STAGES - 1; s++) {
        issue(s, s);
        CP_COMMIT();
    }

    int buf = 0;
    for (int t = 0; t < nChunks; t++) {
        CP_WAIT(STAGES - 2);
        __syncthreads();

        const uint32_t sa = smem_base + (uint32_t)buf * (STAGE_WORDS * 4);
        const uint32_t sb = sa + 2048 * 4;

        if (t + STAGES - 1 < nChunks) {
            int pbuf = buf + STAGES - 1;
            if (pbuf >= STAGES) pbuf -= STAGES;
            issue(t + STAGES - 1, pbuf);
        }
        CP_COMMIT();

#pragma unroll
        for (int s = 0; s < 2; s++) { // two K=16 steps per 32-half chunk
            const uint32_t w0 = 8 * s;
            uint32_t af[4][4];
#pragma unroll
            for (int i = 0; i < 4; i++) {
                const uint32_t g = (w0 + 4 * a_kg) ^ (aw[i] >> 16);
                ldsm4(af[i][0], af[i][1], af[i][2], af[i][3],
                      sa + (((aw[i] & 0xffffu) + g) << 2));
            }
            uint32_t bf[4][2];
#pragma unroll
            for (int jp = 0; jp < 2; jp++) {
                const uint32_t g = (w0 + 4 * b_kg) ^ (bw[jp] >> 16);
                ldsm4(bf[2 * jp][0], bf[2 * jp][1], bf[2 * jp + 1][0],
                      bf[2 * jp + 1][1],
                      sb + (((bw[jp] & 0xffffu) + g) << 2));
            }
#pragma unroll
            for (int i = 0; i < 4; i++)
#pragma unroll
                for (int j = 0; j < 4; j++) mma_f16(acc[i][j], af[i], bf[j]);
        }
        if (++buf == STAGES) buf = 0;
    }

    // Epilogue
#pragma unroll
    for (int i = 0; i < 4; i++) {
        const int m = bm + wr * 64 + i * 16 + gid;
#pragma unroll
        for (int j = 0; j < 4; j++) {
            const int col = bn + wc * 32 + j * 8 + 2 * tig;
            if (EPI == 1) {
                __half* Ch = (__half*)Cv;
                *reinterpret_cast<__half2*>(Ch + (size_t)m * ldc + col) =
                    __floats2half2_rn(acc[i][j][0], acc[i][j][1]);
                *reinterpret_cast<__half2*>(Ch + (size_t)(m + 8) * ldc + col) =
                    __floats2half2_rn(acc[i][j][2], acc[i][j][3]);
            } else if (EPI == 2) {
                __half* Ch = (__half*)Cv;
                const float e00 = (col     <= m) ? __expf(fmaf(acc[i][j][0], SCALE, -EXPC)) : 0.0f;
                const float e01 = (col + 1 <= m) ? __expf(fmaf(acc[i][j][1], SCALE, -EXPC)) : 0.0f;
                const float e10 = (col     <= m + 8) ? __expf(fmaf(acc[i][j][2], SCALE, -EXPC)) : 0.0f;
                const float e11 = (col + 1 <= m + 8) ? __expf(fmaf(acc[i][j][3], SCALE, -EXPC)) : 0.0f;
                *reinterpret_cast<__half2*>(Ch + (size_t)m * ldc + col) =
                    __floats2half2_rn(e00, e01);
                *reinterpret_cast<__half2*>(Ch + (size_t)(m + 8) * ldc + col) =
                    __floats2half2_rn(e10, e11);
            } else {
                float* Cf = (float*)Cv;
                const float r0 = aux[m];
                const float r1 = aux[m + 8];
                *reinterpret_cast<float2*>(Cf + (size_t)m * ldc + col) =
                    make_float2(acc[i][j][0] * r0, acc[i][j][1] * r0);
                *reinterpret_cast<float2*>(Cf + (size_t)(m + 8) * ldc + col) =
                    make_float2(acc[i][j][2] * r1, acc[i][j][3] * r1);
            }
        }
    }
}

// ---------------------------------------------------------------------------
// Kernel 0a: X fp32 -> fp16
// ---------------------------------------------------------------------------
__global__ __launch_bounds__(256) void cvtx_kernel(const float4* __restrict__ src,
                                                   int n4) {
    uint2* dst = reinterpret_cast<uint2*>(g_x);
    const int stride = gridDim.x * blockDim.x;
    for (int i = blockIdx.x * blockDim.x + threadIdx.x; i < n4; i += stride) {
        const float4 v = src[i];
        __half2 h0 = __floats2half2_rn(v.x, v.y);
        __half2 h1 = __floats2half2_rn(v.z, v.w);
        uint2 u;
        u.x = *reinterpret_cast<uint32_t*>(&h0);
        u.y = *reinterpret_cast<uint32_t*>(&h1);
        dst[i] = u;
    }
}

// ---------------------------------------------------------------------------
// Kernel 0b: W fp32 [k][n] -> fp16 W^T [n][k], 32x32 smem tiles, z = weight.
// ---------------------------------------------------------------------------
__global__ __launch_bounds__(256) void wt_kernel(const float* __restrict__ Wq,
                                                 const float* __restrict__ Wk,
                                                 const float* __restrict__ Wv) {
    __shared__ float tile[32][33];
    const float* W = (blockIdx.z == 0) ? Wq : (blockIdx.z == 1) ? Wk : Wv;
    __half* Wt = g_wt[blockIdx.z];
    const int n0 = blockIdx.x * 32, k0 = blockIdx.y * 32;
    const int c = threadIdx.x & 31, r8 = threadIdx.x >> 5;
#pragma unroll
    for (int r = r8; r < 32; r += 8)
        tile[r][c] = W[(size_t)(k0 + r) * D + n0 + c];
    __syncthreads();
#pragma unroll
    for (int r = r8; r < 32; r += 8)
        Wt[(size_t)(n0 + r) * D + k0 + c] = __float2half_rn(tile[c][r]);
}

// ---------------------------------------------------------------------------
// Kernel 0c: V fp16 [b][t][d] -> V^T [b][d][t]
// ---------------------------------------------------------------------------
__global__ __launch_bounds__(256) void vt_kernel() {
    __shared__ __half tile[32][33];
    const int b = blockIdx.z;
    const __half* V = g_v + (size_t)b * T * D;
    __half* Vt = g_vt + (size_t)b * D * T;
    const int t0 = blockIdx.x * 32, d0 = blockIdx.y * 32;
    const int c = threadIdx.x & 31, r8 = threadIdx.x >> 5;
#pragma unroll
    for (int r = r8; r < 32; r += 8)
        tile[r][c] = V[(size_t)(t0 + r) * D + d0 + c];
    __syncthreads();
#pragma unroll
    for (int r = r8; r < 32; r += 8)
        Vt[(size_t)(d0 + r) * T + t0 + c] = tile[c][r];
}

// ---------------------------------------------------------------------------
// Kernel 1: fused QKV projection: g_x @ g_wt[z]^T -> fp16 Q/K/V.
// ---------------------------------------------------------------------------
__global__ __launch_bounds__(256, 2) void proj_kernel() {
    __half* C = (blockIdx.z == 0) ? g_q : (blockIdx.z == 1) ? g_k : g_v;
    hgemm<1>(g_x, g_wt[blockIdx.z], C, nullptr, D, D, D, blockIdx.y * 128,
             blockIdx.x * 128, D / 32);
}

// ---------------------------------------------------------------------------
// Kernel 2: unnormalized masked probs P[b] = exp(QK^T/32 - 5) (causal).
// Writes fp16; zero above the diagonal. Skips tiles fully above diagonal.
// ---------------------------------------------------------------------------
__global__ __launch_bounds__(256, 2) void scores_kernel() {
    const int qm = blockIdx.y;
    const int kn = blockIdx.x;
    if (kn > qm) return;
    const int b = blockIdx.z;
    hgemm<2>(g_q + (size_t)b * T * D, g_k + (size_t)b * T * D,
             g_ph + (size_t)b * T * T, nullptr, D, D, T, qm * 128, kn * 128,
             D / 32);
}

// ---------------------------------------------------------------------------
// Kernel 3: row sums of P (fp16) -> 1/sum (fp32). Deterministic.
// ---------------------------------------------------------------------------
__global__ __launch_bounds__(256) void rowsum_kernel() {
    __shared__ float reds[8];
    const int row = blockIdx.x;
    const int b = row >> 11;
    const int q = row & 2047;
    const int nup = (((q >> 7) + 1) << 7); // round_up(q+1, 128)
    const __half2* P2 = reinterpret_cast<const __half2*>(
        g_ph + (size_t)b * T * T + (size_t)q * T);

    const int tid = threadIdx.x;
    const int lane = tid & 31;
    const int wid = tid >> 5;

    float s = 0.0f;
    for (int j = tid; j < (nup >> 1); j += 256) {
        const float2 v = __half22float2(P2[j]);
        s += v.x + v.y;
    }
#pragma unroll
    for (int k = 16; k > 0; k >>= 1)
        s += __shfl_xor_sync(0xffffffffu, s, k);
    if (lane == 0) reds[wid] = s;
    __syncthreads();
    if (tid == 0) {
        float tot = 0.0f;
#pragma unroll
        for (int w = 0; w < 8; w++) tot += reds[w];
        g_rinv[row] = 1.0f / tot;
    }
}

// ---------------------------------------------------------------------------
// Kernel 4: O[b] = (P[b] @ V[b]) * rinv, k-truncated at the diagonal.
// Longest q-blocks launched first.
// ---------------------------------------------------------------------------
__global__ __launch_bounds__(256, 2) void pv_kernel(float* __restrict__ O) {
    const int b = blockIdx.z;
    const int qm = (gridDim.y - 1) - blockIdx.y;
    hgemm<3>(g_ph + (size_t)b * T * T, g_vt + (size_t)b * D * T,
             O + (size_t)b * T * D, g_rinv + (size_t)b * T, T, T, D,
             qm * 128, blockIdx.x * 128, (qm + 1) * 4);
}

// ---------------------------------------------------------------------------
extern "C" void kernel_launch(void* const* d_in, const int* in_sizes, int n_in,
                              void* d_out, int out_size) {
    (void)in_sizes; (void)n_in; (void)out_size;
    const float4* X  = (const float4*)d_in[0];
    const float*  Wq = (const float*)d_in[1];
    const float*  Wk = (const float*)d_in[2];
    const float*  Wv = (const float*)d_in[3];
    float* O = (float*)d_out;

    cudaFuncSetAttribute(proj_kernel,
                         cudaFuncAttributeMaxDynamicSharedMemorySize,
                         SMEM_BYTES);
    cudaFuncSetAttribute(scores_kernel,
                         cudaFuncAttributeMaxDynamicSharedMemorySize,
                         SMEM_BYTES);
    cudaFuncSetAttribute(pv_kernel,
                         cudaFuncAttributeMaxDynamicSharedMemorySize,
                         SMEM_BYTES);

    cvtx_kernel<<<1024, 256>>>(X, MPROJ * D / 4);
    wt_kernel<<<dim3(D / 32, D / 32, 3), 256>>>(Wq, Wk, Wv);

    proj_kernel<<<dim3(D / 128, MPROJ / 128, 3), 256, SMEM_BYTES>>>();
    vt_kernel<<<dim3(T / 32, D / 32, B), 256>>>();
    scores_kernel<<<dim3(T / 128, T / 128, B), 256, SMEM_BYTES>>>();
    rowsum_kernel<<<dim3(B * T), 256>>>();
    pv_kernel<<<dim3(D / 128, T / 128, B), 256, SMEM_BYTES>>>(O);
}

// round 9
// speedup vs baseline: 1.1990x; 1.0072x over previous
#include <cuda_runtime.h>
#include <cuda_fp16.h>
#include <math.h>
#include <stdint.h>

// ---------------------------------------------------------------------------
// Problem constants
// ---------------------------------------------------------------------------
namespace {
constexpr int B = 4;
constexpr int T = 2048;
constexpr int D = 1024;      // D_IN == D_OUT
constexpr int MPROJ = B * T; // 8192

// Scratch (allocation-free: __device__ globals)
__device__ __half g_x [(size_t)MPROJ * D];   // 16 MB  fp16 input
__device__ __half g_wt[3][(size_t)D * D];    // 6 MB   fp16 W^T (n-major)
__device__ __half g_q [(size_t)B * T * D];   // 16 MB
__device__ __half g_k [(size_t)B * T * D];   // 16 MB
__device__ __half g_vt[(size_t)B * D * T];   // 16 MB  V^T per batch
__device__ __half g_ph[(size_t)B * T * T];   // 32 MB  unnormalized probs fp16
} // namespace

// ---------------------------------------------------------------------------
// Helpers
// ---------------------------------------------------------------------------
__device__ __forceinline__ uint32_t smem_u32(const void* p) {
    uint32_t a;
    asm("{ .reg .u64 t; cvta.to.shared.u64 t, %1; cvt.u32.u64 %0, t; }"
        : "=r"(a) : "l"(p));
    return a;
}

__device__ __forceinline__ void cp16(uint32_t dst, const void* src) {
    asm volatile("cp.async.cg.shared.global [%0], [%1], 16;"
                 :: "r"(dst), "l"(src) : "memory");
}
#define CP_COMMIT()  asm volatile("cp.async.commit_group;" ::: "memory")
#define CP_WAIT(N)   asm volatile("cp.async.wait_group %0;" :: "n"(N) : "memory")
#define CP_WAIT_ALL() asm volatile("cp.async.wait_group 0;" ::: "memory")

__device__ __forceinline__ void ldsm4(uint32_t& r0, uint32_t& r1,
                                      uint32_t& r2, uint32_t& r3,
                                      uint32_t addr) {
    asm volatile("ldmatrix.sync.aligned.m8n8.x4.shared.b16 {%0,%1,%2,%3}, [%4];"
                 : "=r"(r0), "=r"(r1), "=r"(r2), "=r"(r3) : "r"(addr));
}

__device__ __forceinline__ void mma_f16(float c[4], const uint32_t a[4],
                                        const uint32_t b[2]) {
    asm volatile(
        "mma.sync.aligned.m16n8k16.row.col.f32.f16.f16.f32 "
        "{%0,%1,%2,%3}, {%4,%5,%6,%7}, {%8,%9}, {%0,%1,%2,%3};"
        : "+f"(c[0]), "+f"(c[1]), "+f"(c[2]), "+f"(c[3])
        : "r"(a[0]), "r"(a[1]), "r"(a[2]), "r"(a[3]), "r"(b[0]), "r"(b[1]));
}

// ---------------------------------------------------------------------------
// fp16 mma.sync GEMM core ("NT": both operands K-major).
//   C[m,n] += A[m,k] * Bp[n,k]
// CTA tile 128x128, BK=32 halves, 256 threads (8 warps, 2x4 grid),
// warp tile 64x32. ldmatrix.x4 fragment loads from XOR-swizzled smem.
// 3-stage cp.async pipeline; stage = 16 KB; 48 KB smem -> 2 CTAs/SM.
// EPI: 1 = plain fp16 stores (Q/K proj)
//      2 = exp(s*SCALE - EXPC) with causal mask, fp16 stores (scores)
//      3 = fp32 stores scaled by inline per-row 1/sum of A (pv)
//      4 = fp16 transposed store via smem -> g_vt (V proj)
// ---------------------------------------------------------------------------
constexpr int STAGES = 3;
constexpr int STAGE_WORDS = 4096;  // 16 KB / 4
constexpr int SMEM_BYTES = STAGES * STAGE_WORDS * 4; // 49152
constexpr float SCALE = 0.03125f;  // 1/sqrt(1024)
constexpr float EXPC = 5.0f;       // fixed exp offset (cancels in normalize)

template <int EPI>
__device__ __forceinline__ void hgemm(const __half* __restrict__ A,
                                      const __half* __restrict__ Bp,
                                      void* __restrict__ Cv,
                                      int lda, int ldb, int ldc,
                                      int bm, int bn, int nChunks) {
    extern __shared__ float sm[];
    const uint32_t smem_base = smem_u32(sm);

    const int tid = threadIdx.x;
    const int lane = tid & 31;
    const int wid = tid >> 5;
    const int wr = wid >> 2;     // 0..1  (64-row slab)
    const int wc = wid & 3;      // 0..3  (32-col slab)
    const int gid = lane >> 2;   // 0..7
    const int tig = lane & 3;    // 0..3

    // ldmatrix lane roles (mapping validated R6/R7)
    const int a_row_off = ((lane >> 3) & 1) * 8 + (lane & 7);
    const int a_kg = lane >> 4;
    const int b_row_off = (lane >> 4) * 8 + (lane & 7);
    const int b_kg = (lane >> 3) & 1;

    auto issue = [&](int chunk, int buf) {
        const int k0 = chunk * 32;
        const uint32_t sA = smem_base + (uint32_t)buf * (STAGE_WORDS * 4);
        const uint32_t sB = sA + 2048 * 4;
#pragma unroll
        for (int l = 0; l < 2; l++) {               // A: 128 rows x 32 halves
            const int idx = tid + l * 256;
            const int m = idx >> 2, c = idx & 3;
            const uint32_t sw = ((m >> 1) & 3) << 2;
            cp16(sA + (uint32_t)(m * 16 + ((4 * c) ^ sw)) * 4,
                 A + (size_t)(bm + m) * lda + k0 + 8 * c);
        }
#pragma unroll
        for (int l = 0; l < 2; l++) {               // B: 128 rows x 32 halves
            const int idx = tid + l * 256;
            const int n = idx >> 2, c = idx & 3;
            const uint32_t sw = ((n >> 1) & 3) << 2;
            cp16(sB + (uint32_t)(n * 16 + ((4 * c) ^ sw)) * 4,
                 Bp + (size_t)(bn + n) * ldb + k0 + 8 * c);
        }
    };

    float acc[4][4][4];
#pragma unroll
    for (int i = 0; i < 4; i++)
#pragma unroll
        for (int j = 0; j < 4; j++)
#pragma unroll
            for (int e = 0; e < 4; e++) acc[i][j][e] = 0.0f;

    float rsum[8]; // EPI==3: per-row A sums (rows i*16+gid, i*16+gid+8)
#pragma unroll
    for (int r = 0; r < 8; r++) rsum[r] = 0.0f;

    // Per-lane invariant fragment address pieces: low 16 = row*16, hi = swizzle
    uint32_t aw[4], bw[2];
#pragma unroll
    for (int i = 0; i < 4; i++) {
        const int row = wr * 64 + i * 16 + a_row_off;
        aw[i] = (uint32_t)(row * 16) | (((row >> 1) & 3) << 2) << 16;
    }
#pragma unroll
    for (int jp = 0; jp < 2; jp++) {
        const int row = wc * 32 + jp * 16 + b_row_off;
        bw[jp] = (uint32_t)(row * 16) | (((row >> 1) & 3) << 2) << 16;
    }

    // Prologue (nChunks >= 4 always)
#pragma unroll
    for (int s = 0; s < STAGES - 1; s++) {
        issue(s, s);
        CP_COMMIT();
    }

    int buf = 0;
    for (int t = 0; t < nChunks; t++) {
        CP_WAIT(STAGES - 2);
        __syncthreads();

        const uint32_t sa = smem_base + (uint32_t)buf * (STAGE_WORDS * 4);
        const uint32_t sb = sa + 2048 * 4;

        if (t + STAGES - 1 < nChunks) {
            int pbuf = buf + STAGES - 1;
            if (pbuf >= STAGES) pbuf -= STAGES;
            issue(t + STAGES - 1, pbuf);
        }
        CP_COMMIT();

#pragma unroll
        for (int s = 0; s < 2; s++) { // two K=16 steps per 32-half chunk
            const uint32_t w0 = 8 * s;
            uint32_t af[4][4];
#pragma unroll
            for (int i = 0; i < 4; i++) {
                const uint32_t g = (w0 + 4 * a_kg) ^ (aw[i] >> 16);
                ldsm4(af[i][0], af[i][1], af[i][2], af[i][3],
                      sa + (((aw[i] & 0xffffu) + g) << 2));
            }
            if (EPI == 3) {
                // Row sums of A fragments (P values): rows gid / gid+8 per i.
#pragma unroll
                for (int i = 0; i < 4; i++) {
                    const __half2 h0 = __hadd2(
                        *reinterpret_cast<__half2*>(&af[i][0]),
                        *reinterpret_cast<__half2*>(&af[i][2]));
                    const __half2 h1 = __hadd2(
                        *reinterpret_cast<__half2*>(&af[i][1]),
                        *reinterpret_cast<__half2*>(&af[i][3]));
                    const float2 f0 = __half22float2(h0);
                    const float2 f1 = __half22float2(h1);
                    rsum[2 * i]     += f0.x + f0.y;
                    rsum[2 * i + 1] += f1.x + f1.y;
                }
            }
            uint32_t bf[4][2];
#pragma unroll
            for (int jp = 0; jp < 2; jp++) {
                const uint32_t g = (w0 + 4 * b_kg) ^ (bw[jp] >> 16);
                ldsm4(bf[2 * jp][0], bf[2 * jp][1], bf[2 * jp + 1][0],
                      bf[2 * jp + 1][1],
                      sb + (((bw[jp] & 0xffffu) + g) << 2));
            }
#pragma unroll
            for (int i = 0; i < 4; i++)
#pragma unroll
                for (int j = 0; j < 4; j++) mma_f16(acc[i][j], af[i], bf[j]);
        }
        if (++buf == STAGES) buf = 0;
    }

    if (EPI == 3) {
        // Complete row sums across the 4-lane k-groups (same gid), invert.
#pragma unroll
        for (int r = 0; r < 8; r++) {
            rsum[r] += __shfl_xor_sync(0xffffffffu, rsum[r], 1);
            rsum[r] += __shfl_xor_sync(0xffffffffu, rsum[r], 2);
            rsum[r] = 1.0f / rsum[r];
        }
    }

    if (EPI == 4) {
        // Transpose the CTA tile through smem, write g_vt coalesced.
        CP_WAIT_ALL();
        __syncthreads();
        __half* st = reinterpret_cast<__half*>(sm); // [n:128][m:144 halves]
#pragma unroll
        for (int i = 0; i < 4; i++) {
            const int m = wr * 64 + i * 16 + gid;
#pragma unroll
            for (int j = 0; j < 4; j++) {
                const int col = wc * 32 + j * 8 + 2 * tig;
                st[col * 144 + m]           = __float2half_rn(acc[i][j][0]);
                st[(col + 1) * 144 + m]     = __float2half_rn(acc[i][j][1]);
                st[col * 144 + m + 8]       = __float2half_rn(acc[i][j][2]);
                st[(col + 1) * 144 + m + 8] = __float2half_rn(acc[i][j][3]);
            }
        }
        __syncthreads();
        const int row = tid >> 1;   // local n (output d)
        const int p = tid & 1;
        const int b = bm >> 11;
        const int t0 = bm & 2047;
        __half* Vt = g_vt + (size_t)b * D * T + (size_t)(bn + row) * T + t0;
#pragma unroll
        for (int c = 0; c < 8; c++) {
            const int h0 = (2 * c + p) * 8;
            const uint4 v =
                *reinterpret_cast<const uint4*>(st + row * 144 + h0);
            *reinterpret_cast<uint4*>(Vt + h0) = v;
        }
        return;
    }

    // Epilogue (EPI 1/2/3)
#pragma unroll
    for (int i = 0; i < 4; i++) {
        const int m = bm + wr * 64 + i * 16 + gid;
#pragma unroll
        for (int j = 0; j < 4; j++) {
            const int col = bn + wc * 32 + j * 8 + 2 * tig;
            if (EPI == 1) {
                __half* Ch = (__half*)Cv;
                *reinterpret_cast<__half2*>(Ch + (size_t)m * ldc + col) =
                    __floats2half2_rn(acc[i][j][0], acc[i][j][1]);
                *reinterpret_cast<__half2*>(Ch + (size_t)(m + 8) * ldc + col) =
                    __floats2half2_rn(acc[i][j][2], acc[i][j][3]);
            } else if (EPI == 2) {
                __half* Ch = (__half*)Cv;
                const float e00 = (col     <= m) ? __expf(fmaf(acc[i][j][0], SCALE, -EXPC)) : 0.0f;
                const float e01 = (col + 1 <= m) ? __expf(fmaf(acc[i][j][1], SCALE, -EXPC)) : 0.0f;
                const float e10 = (col     <= m + 8) ? __expf(fmaf(acc[i][j][2], SCALE, -EXPC)) : 0.0f;
                const float e11 = (col + 1 <= m + 8) ? __expf(fmaf(acc[i][j][3], SCALE, -EXPC)) : 0.0f;
                *reinterpret_cast<__half2*>(Ch + (size_t)m * ldc + col) =
                    __floats2half2_rn(e00, e01);
                *reinterpret_cast<__half2*>(Ch + (size_t)(m + 8) * ldc + col) =
                    __floats2half2_rn(e10, e11);
            } else {
                float* Cf = (float*)Cv;
                const float r0 = rsum[2 * i];
                const float r1 = rsum[2 * i + 1];
                *reinterpret_cast<float2*>(Cf + (size_t)m * ldc + col) =
                    make_float2(acc[i][j][0] * r0, acc[i][j][1] * r0);
                *reinterpret_cast<float2*>(Cf + (size_t)(m + 8) * ldc + col) =
                    make_float2(acc[i][j][2] * r1, acc[i][j][3] * r1);
            }
        }
    }
}

// ---------------------------------------------------------------------------
// Kernel 0a: X fp32 -> fp16
// ---------------------------------------------------------------------------
__global__ __launch_bounds__(256) void cvtx_kernel(const float4* __restrict__ src,
                                                   int n4) {
    uint2* dst = reinterpret_cast<uint2*>(g_x);
    const int stride = gridDim.x * blockDim.x;
    for (int i = blockIdx.x * blockDim.x + threadIdx.x; i < n4; i += stride) {
        const float4 v = src[i];
        __half2 h0 = __floats2half2_rn(v.x, v.y);
        __half2 h1 = __floats2half2_rn(v.z, v.w);
        uint2 u;
        u.x = *reinterpret_cast<uint32_t*>(&h0);
        u.y = *reinterpret_cast<uint32_t*>(&h1);
        dst[i] = u;
    }
}

// ---------------------------------------------------------------------------
// Kernel 0b: W fp32 [k][n] -> fp16 W^T [n][k], 32x32 smem tiles, z = weight.
// ---------------------------------------------------------------------------
__global__ __launch_bounds__(256) void wt_kernel(const float* __restrict__ Wq,
                                                 const float* __restrict__ Wk,
                                                 const float* __restrict__ Wv) {
    __shared__ float tile[32][33];
    const float* W = (blockIdx.z == 0) ? Wq : (blockIdx.z == 1) ? Wk : Wv;
    __half* Wt = g_wt[blockIdx.z];
    const int n0 = blockIdx.x * 32, k0 = blockIdx.y * 32;
    const int c = threadIdx.x & 31, r8 = threadIdx.x >> 5;
#pragma unroll
    for (int r = r8; r < 32; r += 8)
        tile[r][c] = W[(size_t)(k0 + r) * D + n0 + c];
    __syncthreads();
#pragma unroll
    for (int r = r8; r < 32; r += 8)
        Wt[(size_t)(n0 + r) * D + k0 + c] = __float2half_rn(tile[c][r]);
}

// ---------------------------------------------------------------------------
// Kernel 1a: Q/K projection: g_x @ g_wt[z]^T -> fp16 (z = 0,1).
// ---------------------------------------------------------------------------
__global__ __launch_bounds__(256, 2) void projqk_kernel() {
    __half* C = (blockIdx.z == 0) ? g_q : g_k;
    hgemm<1>(g_x, g_wt[blockIdx.z], C, D, D, D, blockIdx.y * 128,
             blockIdx.x * 128, D / 32);
}

// ---------------------------------------------------------------------------
// Kernel 1b: V projection with transposed store directly into g_vt.
// ---------------------------------------------------------------------------
__global__ __launch_bounds__(256, 2) void projv_kernel() {
    hgemm<4>(g_x, g_wt[2], nullptr, D, D, 0, blockIdx.y * 128,
             blockIdx.x * 128, D / 32);
}

// ---------------------------------------------------------------------------
// Kernel 2: unnormalized masked probs P[b] = exp(QK^T/32 - 5) (causal).
// Writes fp16; zero above the diagonal. Skips tiles fully above diagonal.
// ---------------------------------------------------------------------------
__global__ __launch_bounds__(256, 2) void scores_kernel() {
    const int qm = blockIdx.y;
    const int kn = blockIdx.x;
    if (kn > qm) return;
    const int b = blockIdx.z;
    hgemm<2>(g_q + (size_t)b * T * D, g_k + (size_t)b * T * D,
             g_ph + (size_t)b * T * T, D, D, T, qm * 128, kn * 128, D / 32);
}

// ---------------------------------------------------------------------------
// Kernel 3: O[b] = (P[b] @ V[b]) normalized by inline row sums; k-loop
// truncated at the diagonal. Longest q-blocks launched first.
// ---------------------------------------------------------------------------
__global__ __launch_bounds__(256, 2) void pv_kernel(float* __restrict__ O) {
    const int b = blockIdx.z;
    const int qm = (gridDim.y - 1) - blockIdx.y;
    hgemm<3>(g_ph + (size_t)b * T * T, g_vt + (size_t)b * D * T,
             O + (size_t)b * T * D, T, T, D, qm * 128, blockIdx.x * 128,
             (qm + 1) * 4);
}

// ---------------------------------------------------------------------------
extern "C" void kernel_launch(void* const* d_in, const int* in_sizes, int n_in,
                              void* d_out, int out_size) {
    (void)in_sizes; (void)n_in; (void)out_size;
    const float4* X  = (const float4*)d_in[0];
    const float*  Wq = (const float*)d_in[1];
    const float*  Wk = (const float*)d_in[2];
    const float*  Wv = (const float*)d_in[3];
    float* O = (float*)d_out;

    cudaFuncSetAttribute(projqk_kernel,
                         cudaFuncAttributeMaxDynamicSharedMemorySize,
                         SMEM_BYTES);
    cudaFuncSetAttribute(projv_kernel,
                         cudaFuncAttributeMaxDynamicSharedMemorySize,
                         SMEM_BYTES);
    cudaFuncSetAttribute(scores_kernel,
                         cudaFuncAttributeMaxDynamicSharedMemorySize,
                         SMEM_BYTES);
    cudaFuncSetAttribute(pv_kernel,
                         cudaFuncAttributeMaxDynamicSharedMemorySize,
                         SMEM_BYTES);

    cvtx_kernel<<<1024, 256>>>(X, MPROJ * D / 4);
    wt_kernel<<<dim3(D / 32, D / 32, 3), 256>>>(Wq, Wk, Wv);

    projqk_kernel<<<dim3(D / 128, MPROJ / 128, 2), 256, SMEM_BYTES>>>();
    projv_kernel<<<dim3(D / 128, MPROJ / 128), 256, SMEM_BYTES>>>();
    scores_kernel<<<dim3(T / 128, T / 128, B), 256, SMEM_BYTES>>>();
    pv_kernel<<<dim3(D / 128, T / 128, B), 256, SMEM_BYTES>>>(O);
}

// round 10
// speedup vs baseline: 1.2865x; 1.0729x over previous
#include <cuda_runtime.h>
#include <cuda_fp16.h>
#include <math.h>
#include <stdint.h>

// ---------------------------------------------------------------------------
// Problem constants
// ---------------------------------------------------------------------------
namespace {
constexpr int B = 4;
constexpr int T = 2048;
constexpr int D = 1024;      // D_IN == D_OUT
constexpr int MPROJ = B * T; // 8192

// Scratch (allocation-free: __device__ globals)
__device__ __half g_x  [(size_t)MPROJ * D];  // 16 MB  fp16 input
__device__ __half g_w16[2][(size_t)D * D];   // 4 MB   fp16 Wq, Wk (row-major)
__device__ __half g_wtv[(size_t)D * D];      // 2 MB   fp16 Wv^T (n-major)
__device__ __half g_mt [(size_t)D * D];      // 2 MB   Mt[e][d] = (Wq Wk^T)^T
__device__ __half g_y  [(size_t)B * T * D];  // 16 MB  Y = X (Wq Wk^T)
__device__ __half g_vt [(size_t)B * D * T];  // 16 MB  V^T per batch
__device__ __half g_ph [(size_t)B * T * T];  // 32 MB  unnormalized probs fp16
} // namespace

// ---------------------------------------------------------------------------
// Helpers
// ---------------------------------------------------------------------------
__device__ __forceinline__ uint32_t smem_u32(const void* p) {
    uint32_t a;
    asm("{ .reg .u64 t; cvta.to.shared.u64 t, %1; cvt.u32.u64 %0, t; }"
        : "=r"(a) : "l"(p));
    return a;
}

__device__ __forceinline__ void cp16(uint32_t dst, const void* src) {
    asm volatile("cp.async.cg.shared.global [%0], [%1], 16;"
                 :: "r"(dst), "l"(src) : "memory");
}
#define CP_COMMIT()  asm volatile("cp.async.commit_group;" ::: "memory")
#define CP_WAIT(N)   asm volatile("cp.async.wait_group %0;" :: "n"(N) : "memory")
#define CP_WAIT_ALL() asm volatile("cp.async.wait_group 0;" ::: "memory")

__device__ __forceinline__ void ldsm4(uint32_t& r0, uint32_t& r1,
                                      uint32_t& r2, uint32_t& r3,
                                      uint32_t addr) {
    asm volatile("ldmatrix.sync.aligned.m8n8.x4.shared.b16 {%0,%1,%2,%3}, [%4];"
                 : "=r"(r0), "=r"(r1), "=r"(r2), "=r"(r3) : "r"(addr));
}

__device__ __forceinline__ void mma_f16(float c[4], const uint32_t a[4],
                                        const uint32_t b[2]) {
    asm volatile(
        "mma.sync.aligned.m16n8k16.row.col.f32.f16.f16.f32 "
        "{%0,%1,%2,%3}, {%4,%5,%6,%7}, {%8,%9}, {%0,%1,%2,%3};"
        : "+f"(c[0]), "+f"(c[1]), "+f"(c[2]), "+f"(c[3])
        : "r"(a[0]), "r"(a[1]), "r"(a[2]), "r"(a[3]), "r"(b[0]), "r"(b[1]));
}

// ---------------------------------------------------------------------------
// fp16 mma.sync GEMM core ("NT": both operands K-major).
//   C[m,n] += A[m,k] * Bp[n,k]
// CTA tile 128x128, BK=32 halves, 256 threads (8 warps, 2x4 grid),
// warp tile 64x32. ldmatrix.x4 fragment loads from XOR-swizzled smem.
// 3-stage cp.async pipeline; stage = 16 KB; 48 KB smem -> 2 CTAs/SM.
// EPI: 1 = plain fp16 stores
//      2 = exp(s*SCALE - EXPC) with causal mask, fp16 stores (scores)
//      3 = fp32 stores scaled by inline per-row 1/sum of A (pv)
//      4 = fp16 transposed store via smem -> g_vt (V proj)
// ---------------------------------------------------------------------------
constexpr int STAGES = 3;
constexpr int STAGE_WORDS = 4096;  // 16 KB / 4
constexpr int SMEM_BYTES = STAGES * STAGE_WORDS * 4; // 49152
constexpr float SCALE = 0.03125f;  // 1/sqrt(1024)
constexpr float EXPC = 5.0f;       // fixed exp offset (cancels in normalize)

template <int EPI>
__device__ __forceinline__ void hgemm(const __half* __restrict__ A,
                                      const __half* __restrict__ Bp,
                                      void* __restrict__ Cv,
                                      int lda, int ldb, int ldc,
                                      int bm, int bn, int nChunks) {
    extern __shared__ float sm[];
    const uint32_t smem_base = smem_u32(sm);

    const int tid = threadIdx.x;
    const int lane = tid & 31;
    const int wid = tid >> 5;
    const int wr = wid >> 2;     // 0..1  (64-row slab)
    const int wc = wid & 3;      // 0..3  (32-col slab)
    const int gid = lane >> 2;   // 0..7
    const int tig = lane & 3;    // 0..3

    // ldmatrix lane roles (mapping validated R6/R7)
    const int a_row_off = ((lane >> 3) & 1) * 8 + (lane & 7);
    const int a_kg = lane >> 4;
    const int b_row_off = (lane >> 4) * 8 + (lane & 7);
    const int b_kg = (lane >> 3) & 1;

    auto issue = [&](int chunk, int buf) {
        const int k0 = chunk * 32;
        const uint32_t sA = smem_base + (uint32_t)buf * (STAGE_WORDS * 4);
        const uint32_t sB = sA + 2048 * 4;
#pragma unroll
        for (int l = 0; l < 2; l++) {               // A: 128 rows x 32 halves
            const int idx = tid + l * 256;
            const int m = idx >> 2, c = idx & 3;
            const uint32_t sw = ((m >> 1) & 3) << 2;
            cp16(sA + (uint32_t)(m * 16 + ((4 * c) ^ sw)) * 4,
                 A + (size_t)(bm + m) * lda + k0 + 8 * c);
        }
#pragma unroll
        for (int l = 0; l < 2; l++) {               // B: 128 rows x 32 halves
            const int idx = tid + l * 256;
            const int n = idx >> 2, c = idx & 3;
            const uint32_t sw = ((n >> 1) & 3) << 2;
            cp16(sB + (uint32_t)(n * 16 + ((4 * c) ^ sw)) * 4,
                 Bp + (size_t)(bn + n) * ldb + k0 + 8 * c);
        }
    };

    float acc[4][4][4];
#pragma unroll
    for (int i = 0; i < 4; i++)
#pragma unroll
        for (int j = 0; j < 4; j++)
#pragma unroll
            for (int e = 0; e < 4; e++) acc[i][j][e] = 0.0f;

    float rsum[8]; // EPI==3: per-row A sums (rows i*16+gid, i*16+gid+8)
#pragma unroll
    for (int r = 0; r < 8; r++) rsum[r] = 0.0f;

    // Per-lane invariant fragment address pieces: low 16 = row*16, hi = swizzle
    uint32_t aw[4], bw[2];
#pragma unroll
    for (int i = 0; i < 4; i++) {
        const int row = wr * 64 + i * 16 + a_row_off;
        aw[i] = (uint32_t)(row * 16) | (((row >> 1) & 3) << 2) << 16;
    }
#pragma unroll
    for (int jp = 0; jp < 2; jp++) {
        const int row = wc * 32 + jp * 16 + b_row_off;
        bw[jp] = (uint32_t)(row * 16) | (((row >> 1) & 3) << 2) << 16;
    }

    // Prologue (nChunks >= 4 always)
#pragma unroll
    for (int s = 0; s < STAGES - 1; s++) {
        issue(s, s);
        CP_COMMIT();
    }

    int buf = 0;
    for (int t = 0; t < nChunks; t++) {
        CP_WAIT(STAGES - 2);
        __syncthreads();

        const uint32_t sa = smem_base + (uint32_t)buf * (STAGE_WORDS * 4);
        const uint32_t sb = sa + 2048 * 4;

        if (t + STAGES - 1 < nChunks) {
            int pbuf = buf + STAGES - 1;
            if (pbuf >= STAGES) pbuf -= STAGES;
            issue(t + STAGES - 1, pbuf);
        }
        CP_COMMIT();

#pragma unroll
        for (int s = 0; s < 2; s++) { // two K=16 steps per 32-half chunk
            const uint32_t w0 = 8 * s;
            uint32_t af[4][4];
#pragma unroll
            for (int i = 0; i < 4; i++) {
                const uint32_t g = (w0 + 4 * a_kg) ^ (aw[i] >> 16);
                ldsm4(af[i][0], af[i][1], af[i][2], af[i][3],
                      sa + (((aw[i] & 0xffffu) + g) << 2));
            }
            if (EPI == 3) {
                // Row sums of A fragments (P values): rows gid / gid+8 per i.
#pragma unroll
                for (int i = 0; i < 4; i++) {
                    const __half2 h0 = __hadd2(
                        *reinterpret_cast<__half2*>(&af[i][0]),
                        *reinterpret_cast<__half2*>(&af[i][2]));
                    const __half2 h1 = __hadd2(
                        *reinterpret_cast<__half2*>(&af[i][1]),
                        *reinterpret_cast<__half2*>(&af[i][3]));
                    const float2 f0 = __half22float2(h0);
                    const float2 f1 = __half22float2(h1);
                    rsum[2 * i]     += f0.x + f0.y;
                    rsum[2 * i + 1] += f1.x + f1.y;
                }
            }
            uint32_t bf[4][2];
#pragma unroll
            for (int jp = 0; jp < 2; jp++) {
                const uint32_t g = (w0 + 4 * b_kg) ^ (bw[jp] >> 16);
                ldsm4(bf[2 * jp][0], bf[2 * jp][1], bf[2 * jp + 1][0],
                      bf[2 * jp + 1][1],
                      sb + (((bw[jp] & 0xffffu) + g) << 2));
            }
#pragma unroll
            for (int i = 0; i < 4; i++)
#pragma unroll
                for (int j = 0; j < 4; j++) mma_f16(acc[i][j], af[i], bf[j]);
        }
        if (++buf == STAGES) buf = 0;
    }

    if (EPI == 3) {
        // Complete row sums across the 4-lane k-groups (same gid), invert.
#pragma unroll
        for (int r = 0; r < 8; r++) {
            rsum[r] += __shfl_xor_sync(0xffffffffu, rsum[r], 1);
            rsum[r] += __shfl_xor_sync(0xffffffffu, rsum[r], 2);
            rsum[r] = 1.0f / rsum[r];
        }
    }

    if (EPI == 4) {
        // Transpose the CTA tile through smem, write g_vt coalesced.
        CP_WAIT_ALL();
        __syncthreads();
        __half* st = reinterpret_cast<__half*>(sm); // [n:128][m:144 halves]
#pragma unroll
        for (int i = 0; i < 4; i++) {
            const int m = wr * 64 + i * 16 + gid;
#pragma unroll
            for (int j = 0; j < 4; j++) {
                const int col = wc * 32 + j * 8 + 2 * tig;
                st[col * 144 + m]           = __float2half_rn(acc[i][j][0]);
                st[(col + 1) * 144 + m]     = __float2half_rn(acc[i][j][1]);
                st[col * 144 + m + 8]       = __float2half_rn(acc[i][j][2]);
                st[(col + 1) * 144 + m + 8] = __float2half_rn(acc[i][j][3]);
            }
        }
        __syncthreads();
        const int row = tid >> 1;   // local n (output d)
        const int p = tid & 1;
        const int b = bm >> 11;
        const int t0 = bm & 2047;
        __half* Vt = g_vt + (size_t)b * D * T + (size_t)(bn + row) * T + t0;
#pragma unroll
        for (int c = 0; c < 8; c++) {
            const int h0 = (2 * c + p) * 8;
            const uint4 v =
                *reinterpret_cast<const uint4*>(st + row * 144 + h0);
            *reinterpret_cast<uint4*>(Vt + h0) = v;
        }
        return;
    }

    // Epilogue (EPI 1/2/3)
#pragma unroll
    for (int i = 0; i < 4; i++) {
        const int m = bm + wr * 64 + i * 16 + gid;
#pragma unroll
        for (int j = 0; j < 4; j++) {
            const int col = bn + wc * 32 + j * 8 + 2 * tig;
            if (EPI == 1) {
                __half* Ch = (__half*)Cv;
                *reinterpret_cast<__half2*>(Ch + (size_t)m * ldc + col) =
                    __floats2half2_rn(acc[i][j][0], acc[i][j][1]);
                *reinterpret_cast<__half2*>(Ch + (size_t)(m + 8) * ldc + col) =
                    __floats2half2_rn(acc[i][j][2], acc[i][j][3]);
            } else if (EPI == 2) {
                __half* Ch = (__half*)Cv;
                const float e00 = (col     <= m) ? __expf(fmaf(acc[i][j][0], SCALE, -EXPC)) : 0.0f;
                const float e01 = (col + 1 <= m) ? __expf(fmaf(acc[i][j][1], SCALE, -EXPC)) : 0.0f;
                const float e10 = (col     <= m + 8) ? __expf(fmaf(acc[i][j][2], SCALE, -EXPC)) : 0.0f;
                const float e11 = (col + 1 <= m + 8) ? __expf(fmaf(acc[i][j][3], SCALE, -EXPC)) : 0.0f;
                *reinterpret_cast<__half2*>(Ch + (size_t)m * ldc + col) =
                    __floats2half2_rn(e00, e01);
                *reinterpret_cast<__half2*>(Ch + (size_t)(m + 8) * ldc + col) =
                    __floats2half2_rn(e10, e11);
            } else {
                float* Cf = (float*)Cv;
                const float r0 = rsum[2 * i];
                const float r1 = rsum[2 * i + 1];
                *reinterpret_cast<float2*>(Cf + (size_t)m * ldc + col) =
                    make_float2(acc[i][j][0] * r0, acc[i][j][1] * r0);
                *reinterpret_cast<float2*>(Cf + (size_t)(m + 8) * ldc + col) =
                    make_float2(acc[i][j][2] * r1, acc[i][j][3] * r1);
            }
        }
    }
}

// ---------------------------------------------------------------------------
// Kernel 0a: X fp32 -> fp16
// ---------------------------------------------------------------------------
__global__ __launch_bounds__(256) void cvtx_kernel(const float4* __restrict__ src,
                                                   int n4) {
    uint2* dst = reinterpret_cast<uint2*>(g_x);
    const int stride = gridDim.x * blockDim.x;
    for (int i = blockIdx.x * blockDim.x + threadIdx.x; i < n4; i += stride) {
        const float4 v = src[i];
        __half2 h0 = __floats2half2_rn(v.x, v.y);
        __half2 h1 = __floats2half2_rn(v.z, v.w);
        uint2 u;
        u.x = *reinterpret_cast<uint32_t*>(&h0);
        u.y = *reinterpret_cast<uint32_t*>(&h1);
        dst[i] = u;
    }
}

// ---------------------------------------------------------------------------
// Kernel 0b: Wq/Wk fp32 -> fp16 (no transpose), z selects.
// ---------------------------------------------------------------------------
__global__ __launch_bounds__(256) void cvtw_kernel(const float4* __restrict__ Wq,
                                                   const float4* __restrict__ Wk) {
    const float4* src = (blockIdx.z == 0) ? Wq : Wk;
    uint2* dst = reinterpret_cast<uint2*>(g_w16[blockIdx.z]);
    const int n4 = D * D / 4;
    const int stride = gridDim.x * blockDim.x;
    for (int i = blockIdx.x * blockDim.x + threadIdx.x; i < n4; i += stride) {
        const float4 v = src[i];
        __half2 h0 = __floats2half2_rn(v.x, v.y);
        __half2 h1 = __floats2half2_rn(v.z, v.w);
        uint2 u;
        u.x = *reinterpret_cast<uint32_t*>(&h0);
        u.y = *reinterpret_cast<uint32_t*>(&h1);
        dst[i] = u;
    }
}

// ---------------------------------------------------------------------------
// Kernel 0c: Wv fp32 [k][n] -> fp16 Wv^T [n][k], 32x32 smem tiles.
// ---------------------------------------------------------------------------
__global__ __launch_bounds__(256) void wtv_kernel(const float* __restrict__ Wv) {
    __shared__ float tile[32][33];
    const int n0 = blockIdx.x * 32, k0 = blockIdx.y * 32;
    const int c = threadIdx.x & 31, r8 = threadIdx.x >> 5;
#pragma unroll
    for (int r = r8; r < 32; r += 8)
        tile[r][c] = Wv[(size_t)(k0 + r) * D + n0 + c];
    __syncthreads();
#pragma unroll
    for (int r = r8; r < 32; r += 8)
        g_wtv[(size_t)(n0 + r) * D + k0 + c] = __float2half_rn(tile[c][r]);
}

// ---------------------------------------------------------------------------
// Kernel 1: Mt[e][d] = sum_i Wk[e][i] * Wq[d][i]  (Mt = (Wq Wk^T)^T)
// ---------------------------------------------------------------------------
__global__ __launch_bounds__(256, 2) void mt_kernel() {
    hgemm<1>(g_w16[1], g_w16[0], g_mt, D, D, D, blockIdx.y * 128,
             blockIdx.x * 128, D / 32);
}

// ---------------------------------------------------------------------------
// Kernel 2a: Y = X @ M  (NT against Mt) -> fp16. Replaces the Q projection;
// the K projection is eliminated entirely.
// ---------------------------------------------------------------------------
__global__ __launch_bounds__(256, 2) void projy_kernel() {
    hgemm<1>(g_x, g_mt, g_y, D, D, D, blockIdx.y * 128, blockIdx.x * 128,
             D / 32);
}

// ---------------------------------------------------------------------------
// Kernel 2b: V projection with transposed store directly into g_vt.
// ---------------------------------------------------------------------------
__global__ __launch_bounds__(256, 2) void projv_kernel() {
    hgemm<4>(g_x, g_wtv, nullptr, D, D, 0, blockIdx.y * 128,
             blockIdx.x * 128, D / 32);
}

// ---------------------------------------------------------------------------
// Kernel 3: unnormalized masked probs P[b] = exp(Y X^T / 32 - 5) (causal).
// B operand is the fp16 input X itself. Skips tiles above the diagonal.
// ---------------------------------------------------------------------------
__global__ __launch_bounds__(256, 2) void scores_kernel() {
    const int qm = blockIdx.y;
    const int kn = blockIdx.x;
    if (kn > qm) return;
    const int b = blockIdx.z;
    hgemm<2>(g_y + (size_t)b * T * D, g_x + (size_t)b * T * D,
             g_ph + (size_t)b * T * T, D, D, T, qm * 128, kn * 128, D / 32);
}

// ---------------------------------------------------------------------------
// Kernel 4: O[b] = (P[b] @ V[b]) normalized by inline row sums; k-loop
// truncated at the diagonal. Longest q-blocks launched first.
// ---------------------------------------------------------------------------
__global__ __launch_bounds__(256, 2) void pv_kernel(float* __restrict__ O) {
    const int b = blockIdx.z;
    const int qm = (gridDim.y - 1) - blockIdx.y;
    hgemm<3>(g_ph + (size_t)b * T * T, g_vt + (size_t)b * D * T,
             O + (size_t)b * T * D, T, T, D, qm * 128, blockIdx.x * 128,
             (qm + 1) * 4);
}

// ---------------------------------------------------------------------------
extern "C" void kernel_launch(void* const* d_in, const int* in_sizes, int n_in,
                              void* d_out, int out_size) {
    (void)in_sizes; (void)n_in; (void)out_size;
    const float4* X  = (const float4*)d_in[0];
    const float4* Wq = (const float4*)d_in[1];
    const float4* Wk = (const float4*)d_in[2];
    const float*  Wv = (const float*)d_in[3];
    float* O = (float*)d_out;

    cudaFuncSetAttribute(mt_kernel,
                         cudaFuncAttributeMaxDynamicSharedMemorySize,
                         SMEM_BYTES);
    cudaFuncSetAttribute(projy_kernel,
                         cudaFuncAttributeMaxDynamicSharedMemorySize,
                         SMEM_BYTES);
    cudaFuncSetAttribute(projv_kernel,
                         cudaFuncAttributeMaxDynamicSharedMemorySize,
                         SMEM_BYTES);
    cudaFuncSetAttribute(scores_kernel,
                         cudaFuncAttributeMaxDynamicSharedMemorySize,
                         SMEM_BYTES);
    cudaFuncSetAttribute(pv_kernel,
                         cudaFuncAttributeMaxDynamicSharedMemorySize,
                         SMEM_BYTES);

    cvtx_kernel<<<1024, 256>>>(X, MPROJ * D / 4);
    cvtw_kernel<<<dim3(256, 1, 2), 256>>>(Wq, Wk);
    wtv_kernel<<<dim3(D / 32, D / 32), 256>>>(Wv);

    mt_kernel<<<dim3(D / 128, D / 128), 256, SMEM_BYTES>>>();
    projy_kernel<<<dim3(D / 128, MPROJ / 128), 256, SMEM_BYTES>>>();
    projv_kernel<<<dim3(D / 128, MPROJ / 128), 256, SMEM_BYTES>>>();
    scores_kernel<<<dim3(T / 128, T / 128, B), 256, SMEM_BYTES>>>();
    pv_kernel<<<dim3(D / 128, T / 128, B), 256, SMEM_BYTES>>>(O);
}

// round 11
// speedup vs baseline: 1.3534x; 1.0521x over previous
#include <cuda_runtime.h>
#include <cuda_fp16.h>
#include <math.h>
#include <stdint.h>

// ---------------------------------------------------------------------------
// Problem constants
// ---------------------------------------------------------------------------
namespace {
constexpr int B = 4;
constexpr int T = 2048;
constexpr int D = 1024;      // D_IN == D_OUT
constexpr int MPROJ = B * T; // 8192

// Scratch (allocation-free: __device__ globals)
__device__ __half g_x  [(size_t)MPROJ * D];  // 16 MB  fp16 input
__device__ __half g_w16[2][(size_t)D * D];   // 4 MB   fp16 Wq, Wk (row-major)
__device__ __half g_wtv[(size_t)D * D];      // 2 MB   fp16 Wv^T (n-major)
__device__ __half g_mt [(size_t)D * D];      // 2 MB   Mt[e][d] = (Wq Wk^T)^T
__device__ __half g_y  [(size_t)B * T * D];  // 16 MB  Y = X (Wq Wk^T)
__device__ __half g_vt [(size_t)B * D * T];  // 16 MB  V^T per batch
__device__ __half g_ph [(size_t)B * T * T];  // 32 MB  unnormalized probs fp16
} // namespace

// ---------------------------------------------------------------------------
// Helpers
// ---------------------------------------------------------------------------
__device__ __forceinline__ uint32_t smem_u32(const void* p) {
    uint32_t a;
    asm("{ .reg .u64 t; cvta.to.shared.u64 t, %1; cvt.u32.u64 %0, t; }"
        : "=r"(a) : "l"(p));
    return a;
}

__device__ __forceinline__ void cp16(uint32_t dst, const void* src) {
    asm volatile("cp.async.cg.shared.global [%0], [%1], 16;"
                 :: "r"(dst), "l"(src) : "memory");
}
#define CP_COMMIT()  asm volatile("cp.async.commit_group;" ::: "memory")
#define CP_WAIT(N)   asm volatile("cp.async.wait_group %0;" :: "n"(N) : "memory")
#define CP_WAIT_ALL() asm volatile("cp.async.wait_group 0;" ::: "memory")

__device__ __forceinline__ void ldsm4(uint32_t& r0, uint32_t& r1,
                                      uint32_t& r2, uint32_t& r3,
                                      uint32_t addr) {
    asm volatile("ldmatrix.sync.aligned.m8n8.x4.shared.b16 {%0,%1,%2,%3}, [%4];"
                 : "=r"(r0), "=r"(r1), "=r"(r2), "=r"(r3) : "r"(addr));
}

__device__ __forceinline__ void mma_f16(float c[4], const uint32_t a[4],
                                        const uint32_t b[2]) {
    asm volatile(
        "mma.sync.aligned.m16n8k16.row.col.f32.f16.f16.f32 "
        "{%0,%1,%2,%3}, {%4,%5,%6,%7}, {%8,%9}, {%0,%1,%2,%3};"
        : "+f"(c[0]), "+f"(c[1]), "+f"(c[2]), "+f"(c[3])
        : "r"(a[0]), "r"(a[1]), "r"(a[2]), "r"(a[3]), "r"(b[0]), "r"(b[1]));
}

// ---------------------------------------------------------------------------
// fp16 mma.sync GEMM core ("NT": both operands K-major).
//   C[m,n] += A[m,k] * Bp[n,k]
// CTA tile 128x128, BK=32 halves, 256 threads (8 warps, 2x4 grid),
// warp tile 64x32. ldmatrix.x4 fragment loads from XOR-swizzled smem.
// 3-stage cp.async pipeline; stage = 16 KB; 48 KB smem -> 2 CTAs/SM.
// EPI: 1 = plain fp16 stores
//      2 = exp(s*SCALE - EXPC) with causal mask, fp16 stores (scores)
//      3 = fp32 stores scaled by inline per-row 1/sum of A (pv)
//      4 = fp16 transposed store via smem -> g_vt (V proj)
// ---------------------------------------------------------------------------
constexpr int STAGES = 3;
constexpr int STAGE_WORDS = 4096;  // 16 KB / 4
constexpr int SMEM_BYTES = STAGES * STAGE_WORDS * 4; // 49152
constexpr float SCALE = 0.03125f;  // 1/sqrt(1024)
constexpr float EXPC = 5.0f;       // fixed exp offset (cancels in normalize)

template <int EPI>
__device__ __forceinline__ void hgemm(const __half* __restrict__ A,
                                      const __half* __restrict__ Bp,
                                      void* __restrict__ Cv,
                                      int lda, int ldb, int ldc,
                                      int bm, int bn, int nChunks) {
    extern __shared__ float sm[];
    const uint32_t smem_base = smem_u32(sm);

    const int tid = threadIdx.x;
    const int lane = tid & 31;
    const int wid = tid >> 5;
    const int wr = wid >> 2;     // 0..1  (64-row slab)
    const int wc = wid & 3;      // 0..3  (32-col slab)
    const int gid = lane >> 2;   // 0..7
    const int tig = lane & 3;    // 0..3

    // ldmatrix lane roles (mapping validated R6/R7)
    const int a_row_off = ((lane >> 3) & 1) * 8 + (lane & 7);
    const int a_kg = lane >> 4;
    const int b_row_off = (lane >> 4) * 8 + (lane & 7);
    const int b_kg = (lane >> 3) & 1;

    auto issue = [&](int chunk, int buf) {
        const int k0 = chunk * 32;
        const uint32_t sA = smem_base + (uint32_t)buf * (STAGE_WORDS * 4);
        const uint32_t sB = sA + 2048 * 4;
#pragma unroll
        for (int l = 0; l < 2; l++) {               // A: 128 rows x 32 halves
            const int idx = tid + l * 256;
            const int m = idx >> 2, c = idx & 3;
            const uint32_t sw = ((m >> 1) & 3) << 2;
            cp16(sA + (uint32_t)(m * 16 + ((4 * c) ^ sw)) * 4,
                 A + (size_t)(bm + m) * lda + k0 + 8 * c);
        }
#pragma unroll
        for (int l = 0; l < 2; l++) {               // B: 128 rows x 32 halves
            const int idx = tid + l * 256;
            const int n = idx >> 2, c = idx & 3;
            const uint32_t sw = ((n >> 1) & 3) << 2;
            cp16(sB + (uint32_t)(n * 16 + ((4 * c) ^ sw)) * 4,
                 Bp + (size_t)(bn + n) * ldb + k0 + 8 * c);
        }
    };

    float acc[4][4][4];
#pragma unroll
    for (int i = 0; i < 4; i++)
#pragma unroll
        for (int j = 0; j < 4; j++)
#pragma unroll
            for (int e = 0; e < 4; e++) acc[i][j][e] = 0.0f;

    float rsum[8]; // EPI==3: per-row A sums (rows i*16+gid, i*16+gid+8)
#pragma unroll
    for (int r = 0; r < 8; r++) rsum[r] = 0.0f;

    // Per-lane invariant fragment address pieces: low 16 = row*16, hi = swizzle
    uint32_t aw[4], bw[2];
#pragma unroll
    for (int i = 0; i < 4; i++) {
        const int row = wr * 64 + i * 16 + a_row_off;
        aw[i] = (uint32_t)(row * 16) | (((row >> 1) & 3) << 2) << 16;
    }
#pragma unroll
    for (int jp = 0; jp < 2; jp++) {
        const int row = wc * 32 + jp * 16 + b_row_off;
        bw[jp] = (uint32_t)(row * 16) | (((row >> 1) & 3) << 2) << 16;
    }

    // Prologue (nChunks >= 4 always)
#pragma unroll
    for (int s = 0; s < STAGES - 1; s++) {
        issue(s, s);
        CP_COMMIT();
    }

    int buf = 0;
    for (int t = 0; t < nChunks; t++) {
        CP_WAIT(STAGES - 2);
        __syncthreads();

        const uint32_t sa = smem_base + (uint32_t)buf * (STAGE_WORDS * 4);
        const uint32_t sb = sa + 2048 * 4;

        if (t + STAGES - 1 < nChunks) {
            int pbuf = buf + STAGES - 1;
            if (pbuf >= STAGES) pbuf -= STAGES;
            issue(t + STAGES - 1, pbuf);
        }
        CP_COMMIT();

#pragma unroll
        for (int s = 0; s < 2; s++) { // two K=16 steps per 32-half chunk
            const uint32_t w0 = 8 * s;
            uint32_t af[4][4];
#pragma unroll
            for (int i = 0; i < 4; i++) {
                const uint32_t g = (w0 + 4 * a_kg) ^ (aw[i] >> 16);
                ldsm4(af[i][0], af[i][1], af[i][2], af[i][3],
                      sa + (((aw[i] & 0xffffu) + g) << 2));
            }
            if (EPI == 3) {
                // Row sums of A fragments (P values): rows gid / gid+8 per i.
#pragma unroll
                for (int i = 0; i < 4; i++) {
                    const __half2 h0 = __hadd2(
                        *reinterpret_cast<__half2*>(&af[i][0]),
                        *reinterpret_cast<__half2*>(&af[i][2]));
                    const __half2 h1 = __hadd2(
                        *reinterpret_cast<__half2*>(&af[i][1]),
                        *reinterpret_cast<__half2*>(&af[i][3]));
                    const float2 f0 = __half22float2(h0);
                    const float2 f1 = __half22float2(h1);
                    rsum[2 * i]     += f0.x + f0.y;
                    rsum[2 * i + 1] += f1.x + f1.y;
                }
            }
            uint32_t bf[4][2];
#pragma unroll
            for (int jp = 0; jp < 2; jp++) {
                const uint32_t g = (w0 + 4 * b_kg) ^ (bw[jp] >> 16);
                ldsm4(bf[2 * jp][0], bf[2 * jp][1], bf[2 * jp + 1][0],
                      bf[2 * jp + 1][1],
                      sb + (((bw[jp] & 0xffffu) + g) << 2));
            }
#pragma unroll
            for (int i = 0; i < 4; i++)
#pragma unroll
                for (int j = 0; j < 4; j++) mma_f16(acc[i][j], af[i], bf[j]);
        }
        if (++buf == STAGES) buf = 0;
    }

    if (EPI == 3) {
        // Complete row sums across the 4-lane k-groups (same gid), invert.
#pragma unroll
        for (int r = 0; r < 8; r++) {
            rsum[r] += __shfl_xor_sync(0xffffffffu, rsum[r], 1);
            rsum[r] += __shfl_xor_sync(0xffffffffu, rsum[r], 2);
            rsum[r] = 1.0f / rsum[r];
        }
    }

    if (EPI == 4) {
        // Transpose the CTA tile through smem, write g_vt coalesced.
        CP_WAIT_ALL();
        __syncthreads();
        __half* st = reinterpret_cast<__half*>(sm); // [n:128][m:144 halves]
#pragma unroll
        for (int i = 0; i < 4; i++) {
            const int m = wr * 64 + i * 16 + gid;
#pragma unroll
            for (int j = 0; j < 4; j++) {
                const int col = wc * 32 + j * 8 + 2 * tig;
                st[col * 144 + m]           = __float2half_rn(acc[i][j][0]);
                st[(col + 1) * 144 + m]     = __float2half_rn(acc[i][j][1]);
                st[col * 144 + m + 8]       = __float2half_rn(acc[i][j][2]);
                st[(col + 1) * 144 + m + 8] = __float2half_rn(acc[i][j][3]);
            }
        }
        __syncthreads();
        const int row = tid >> 1;   // local n (output d)
        const int p = tid & 1;
        const int b = bm >> 11;
        const int t0 = bm & 2047;
        __half* Vt = g_vt + (size_t)b * D * T + (size_t)(bn + row) * T + t0;
#pragma unroll
        for (int c = 0; c < 8; c++) {
            const int h0 = (2 * c + p) * 8;
            const uint4 v =
                *reinterpret_cast<const uint4*>(st + row * 144 + h0);
            *reinterpret_cast<uint4*>(Vt + h0) = v;
        }
        return;
    }

    // Epilogue (EPI 1/2/3)
#pragma unroll
    for (int i = 0; i < 4; i++) {
        const int m = bm + wr * 64 + i * 16 + gid;
#pragma unroll
        for (int j = 0; j < 4; j++) {
            const int col = bn + wc * 32 + j * 8 + 2 * tig;
            if (EPI == 1) {
                __half* Ch = (__half*)Cv;
                *reinterpret_cast<__half2*>(Ch + (size_t)m * ldc + col) =
                    __floats2half2_rn(acc[i][j][0], acc[i][j][1]);
                *reinterpret_cast<__half2*>(Ch + (size_t)(m + 8) * ldc + col) =
                    __floats2half2_rn(acc[i][j][2], acc[i][j][3]);
            } else if (EPI == 2) {
                __half* Ch = (__half*)Cv;
                const float e00 = (col     <= m) ? __expf(fmaf(acc[i][j][0], SCALE, -EXPC)) : 0.0f;
                const float e01 = (col + 1 <= m) ? __expf(fmaf(acc[i][j][1], SCALE, -EXPC)) : 0.0f;
                const float e10 = (col     <= m + 8) ? __expf(fmaf(acc[i][j][2], SCALE, -EXPC)) : 0.0f;
                const float e11 = (col + 1 <= m + 8) ? __expf(fmaf(acc[i][j][3], SCALE, -EXPC)) : 0.0f;
                *reinterpret_cast<__half2*>(Ch + (size_t)m * ldc + col) =
                    __floats2half2_rn(e00, e01);
                *reinterpret_cast<__half2*>(Ch + (size_t)(m + 8) * ldc + col) =
                    __floats2half2_rn(e10, e11);
            } else {
                float* Cf = (float*)Cv;
                const float r0 = rsum[2 * i];
                const float r1 = rsum[2 * i + 1];
                *reinterpret_cast<float2*>(Cf + (size_t)m * ldc + col) =
                    make_float2(acc[i][j][0] * r0, acc[i][j][1] * r0);
                *reinterpret_cast<float2*>(Cf + (size_t)(m + 8) * ldc + col) =
                    make_float2(acc[i][j][2] * r1, acc[i][j][3] * r1);
            }
        }
    }
}

// ---------------------------------------------------------------------------
// Kernel 0a: X fp32 -> fp16
// ---------------------------------------------------------------------------
__global__ __launch_bounds__(256) void cvtx_kernel(const float4* __restrict__ src,
                                                   int n4) {
    uint2* dst = reinterpret_cast<uint2*>(g_x);
    const int stride = gridDim.x * blockDim.x;
    for (int i = blockIdx.x * blockDim.x + threadIdx.x; i < n4; i += stride) {
        const float4 v = src[i];
        __half2 h0 = __floats2half2_rn(v.x, v.y);
        __half2 h1 = __floats2half2_rn(v.z, v.w);
        uint2 u;
        u.x = *reinterpret_cast<uint32_t*>(&h0);
        u.y = *reinterpret_cast<uint32_t*>(&h1);
        dst[i] = u;
    }
}

// ---------------------------------------------------------------------------
// Kernel 0b: Wq/Wk fp32 -> fp16 (no transpose), z selects.
// ---------------------------------------------------------------------------
__global__ __launch_bounds__(256) void cvtw_kernel(const float4* __restrict__ Wq,
                                                   const float4* __restrict__ Wk) {
    const float4* src = (blockIdx.z == 0) ? Wq : Wk;
    uint2* dst = reinterpret_cast<uint2*>(g_w16[blockIdx.z]);
    const int n4 = D * D / 4;
    const int stride = gridDim.x * blockDim.x;
    for (int i = blockIdx.x * blockDim.x + threadIdx.x; i < n4; i += stride) {
        const float4 v = src[i];
        __half2 h0 = __floats2half2_rn(v.x, v.y);
        __half2 h1 = __floats2half2_rn(v.z, v.w);
        uint2 u;
        u.x = *reinterpret_cast<uint32_t*>(&h0);
        u.y = *reinterpret_cast<uint32_t*>(&h1);
        dst[i] = u;
    }
}

// ---------------------------------------------------------------------------
// Kernel 0c: Wv fp32 [k][n] -> fp16 Wv^T [n][k], 32x32 smem tiles.
// ---------------------------------------------------------------------------
__global__ __launch_bounds__(256) void wtv_kernel(const float* __restrict__ Wv) {
    __shared__ float tile[32][33];
    const int n0 = blockIdx.x * 32, k0 = blockIdx.y * 32;
    const int c = threadIdx.x & 31, r8 = threadIdx.x >> 5;
#pragma unroll
    for (int r = r8; r < 32; r += 8)
        tile[r][c] = Wv[(size_t)(k0 + r) * D + n0 + c];
    __syncthreads();
#pragma unroll
    for (int r = r8; r < 32; r += 8)
        g_wtv[(size_t)(n0 + r) * D + k0 + c] = __float2half_rn(tile[c][r]);
}

// ---------------------------------------------------------------------------
// Kernel 1: FUSED  Mt = (Wq Wk^T)^T  (64 CTAs, scheduled first)  +
//                  V^T projection   (512 CTAs).
// The two GEMMs are independent; fusing removes the 12%-occupancy mt bubble.
// grid: (8, 72). y<8 -> mt tile; y>=8 -> projv tile (EPI 4).
// ---------------------------------------------------------------------------
__global__ __launch_bounds__(256, 2) void mtprojv_kernel() {
    if (blockIdx.y < 8) {
        // Mt[e][d] = sum_i Wk[e][i] * Wq[d][i]
        hgemm<1>(g_w16[1], g_w16[0], g_mt, D, D, D, blockIdx.y * 128,
                 blockIdx.x * 128, D / 32);
    } else {
        // V^T projection with transposed store directly into g_vt.
        hgemm<4>(g_x, g_wtv, nullptr, D, D, 0, (blockIdx.y - 8) * 128,
                 blockIdx.x * 128, D / 32);
    }
}

// ---------------------------------------------------------------------------
// Kernel 2: Y = X @ M  (NT against Mt) -> fp16. Replaces the Q projection;
// the K projection is eliminated entirely (scores = Y X^T).
// ---------------------------------------------------------------------------
__global__ __launch_bounds__(256, 2) void projy_kernel() {
    hgemm<1>(g_x, g_mt, g_y, D, D, D, blockIdx.y * 128, blockIdx.x * 128,
             D / 32);
}

// ---------------------------------------------------------------------------
// Kernel 3: unnormalized masked probs P[b] = exp(Y X^T / 32 - 5) (causal).
// B operand is the fp16 input X itself. Skips tiles above the diagonal.
// ---------------------------------------------------------------------------
__global__ __launch_bounds__(256, 2) void scores_kernel() {
    const int qm = blockIdx.y;
    const int kn = blockIdx.x;
    if (kn > qm) return;
    const int b = blockIdx.z;
    hgemm<2>(g_y + (size_t)b * T * D, g_x + (size_t)b * T * D,
             g_ph + (size_t)b * T * T, D, D, T, qm * 128, kn * 128, D / 32);
}

// ---------------------------------------------------------------------------
// Kernel 4: O[b] = (P[b] @ V[b]) normalized by inline row sums; k-loop
// truncated at the diagonal. Longest q-blocks launched first.
// ---------------------------------------------------------------------------
__global__ __launch_bounds__(256, 2) void pv_kernel(float* __restrict__ O) {
    const int b = blockIdx.z;
    const int qm = (gridDim.y - 1) - blockIdx.y;
    hgemm<3>(g_ph + (size_t)b * T * T, g_vt + (size_t)b * D * T,
             O + (size_t)b * T * D, T, T, D, qm * 128, blockIdx.x * 128,
             (qm + 1) * 4);
}

// ---------------------------------------------------------------------------
extern "C" void kernel_launch(void* const* d_in, const int* in_sizes, int n_in,
                              void* d_out, int out_size) {
    (void)in_sizes; (void)n_in; (void)out_size;
    const float4* X  = (const float4*)d_in[0];
    const float4* Wq = (const float4*)d_in[1];
    const float4* Wk = (const float4*)d_in[2];
    const float*  Wv = (const float*)d_in[3];
    float* O = (float*)d_out;

    cudaFuncSetAttribute(mtprojv_kernel,
                         cudaFuncAttributeMaxDynamicSharedMemorySize,
                         SMEM_BYTES);
    cudaFuncSetAttribute(projy_kernel,
                         cudaFuncAttributeMaxDynamicSharedMemorySize,
                         SMEM_BYTES);
    cudaFuncSetAttribute(scores_kernel,
                         cudaFuncAttributeMaxDynamicSharedMemorySize,
                         SMEM_BYTES);
    cudaFuncSetAttribute(pv_kernel,
                         cudaFuncAttributeMaxDynamicSharedMemorySize,
                         SMEM_BYTES);

    cvtx_kernel<<<1024, 256>>>(X, MPROJ * D / 4);
    cvtw_kernel<<<dim3(256, 1, 2), 256>>>(Wq, Wk);
    wtv_kernel<<<dim3(D / 32, D / 32), 256>>>(Wv);

    mtprojv_kernel<<<dim3(8, 72), 256, SMEM_BYTES>>>();
    projy_kernel<<<dim3(D / 128, MPROJ / 128), 256, SMEM_BYTES>>>();
    scores_kernel<<<dim3(T / 128, T / 128, B), 256, SMEM_BYTES>>>();
    pv_kernel<<<dim3(D / 128, T / 128, B), 256, SMEM_BYTES>>>(O);
}

// round 12
// speedup vs baseline: 1.4861x; 1.0980x over previous
#include <cuda_runtime.h>
#include <cuda_fp16.h>
#include <math.h>
#include <stdint.h>

// ---------------------------------------------------------------------------
// Problem constants
// ---------------------------------------------------------------------------
namespace {
constexpr int B = 4;
constexpr int T = 2048;
constexpr int D = 1024;      // D_IN == D_OUT
constexpr int MPROJ = B * T; // 8192

// Scratch (allocation-free: __device__ globals)
__device__ __half g_x  [(size_t)MPROJ * D];  // 16 MB  fp16 input
__device__ __half g_w16[2][(size_t)D * D];   // 4 MB   fp16 Wq, Wk (row-major)
__device__ __half g_wtv[(size_t)D * D];      // 2 MB   fp16 Wv^T (n-major)
__device__ __half g_mt [(size_t)D * D];      // 2 MB   Mt[e][d] = (Wq Wk^T)^T
__device__ __half g_y  [(size_t)B * T * D];  // 16 MB  Y = X (Wq Wk^T)
__device__ __half g_vt [(size_t)B * D * T];  // 16 MB  V^T per batch
__device__ __half g_ph [(size_t)B * T * T];  // 32 MB  unnormalized probs fp16
} // namespace

// ---------------------------------------------------------------------------
// Helpers
// ---------------------------------------------------------------------------
__device__ __forceinline__ uint32_t smem_u32(const void* p) {
    uint32_t a;
    asm("{ .reg .u64 t; cvta.to.shared.u64 t, %1; cvt.u32.u64 %0, t; }"
        : "=r"(a) : "l"(p));
    return a;
}

__device__ __forceinline__ void cp16(uint32_t dst, const void* src) {
    asm volatile("cp.async.cg.shared.global [%0], [%1], 16;"
                 :: "r"(dst), "l"(src) : "memory");
}
#define CP_COMMIT()  asm volatile("cp.async.commit_group;" ::: "memory")
#define CP_WAIT(N)   asm volatile("cp.async.wait_group %0;" :: "n"(N) : "memory")
#define CP_WAIT_ALL() asm volatile("cp.async.wait_group 0;" ::: "memory")

__device__ __forceinline__ void ldsm4(uint32_t& r0, uint32_t& r1,
                                      uint32_t& r2, uint32_t& r3,
                                      uint32_t addr) {
    asm volatile("ldmatrix.sync.aligned.m8n8.x4.shared.b16 {%0,%1,%2,%3}, [%4];"
                 : "=r"(r0), "=r"(r1), "=r"(r2), "=r"(r3) : "r"(addr));
}

__device__ __forceinline__ void mma_f16(float c[4], const uint32_t a[4],
                                        const uint32_t b[2]) {
    asm volatile(
        "mma.sync.aligned.m16n8k16.row.col.f32.f16.f16.f32 "
        "{%0,%1,%2,%3}, {%4,%5,%6,%7}, {%8,%9}, {%0,%1,%2,%3};"
        : "+f"(c[0]), "+f"(c[1]), "+f"(c[2]), "+f"(c[3])
        : "r"(a[0]), "r"(a[1]), "r"(a[2]), "r"(a[3]), "r"(b[0]), "r"(b[1]));
}

// ---------------------------------------------------------------------------
// fp16 mma.sync GEMM core ("NT": both operands K-major).
//   C[m,n] += A[m,k] * Bp[n,k]
// CTA tile 128x128, BK=32 halves, 128 threads (4 warps, 2x2 grid),
// warp tile 64x64 (32 HMMA per K16 step -> HMMA:LDSM = 4.0).
// ldmatrix.x4 fragment loads from XOR-swizzled smem.
// 3-stage cp.async pipeline; stage = 16 KB; 48 KB smem -> 2 CTAs/SM.
// EPI: 1 = plain fp16 stores
//      2 = exp(s*SCALE - EXPC) with causal mask, fp16 stores (scores)
//      3 = fp32 stores scaled by inline per-row 1/sum of A (pv)
//      4 = fp16 transposed store via smem -> g_vt (V proj)
// ---------------------------------------------------------------------------
constexpr int STAGES = 3;
constexpr int STAGE_WORDS = 4096;  // 16 KB / 4
constexpr int SMEM_BYTES = STAGES * STAGE_WORDS * 4; // 49152
constexpr int NTHREADS = 128;
constexpr float SCALE = 0.03125f;  // 1/sqrt(1024)
constexpr float EXPC = 5.0f;       // fixed exp offset (cancels in normalize)

template <int EPI>
__device__ __forceinline__ void hgemm(const __half* __restrict__ A,
                                      const __half* __restrict__ Bp,
                                      void* __restrict__ Cv,
                                      int lda, int ldb, int ldc,
                                      int bm, int bn, int nChunks) {
    extern __shared__ float sm[];
    const uint32_t smem_base = smem_u32(sm);

    const int tid = threadIdx.x;
    const int lane = tid & 31;
    const int wid = tid >> 5;
    const int wr = wid >> 1;     // 0..1  (64-row slab)
    const int wc = wid & 1;      // 0..1  (64-col slab)
    const int gid = lane >> 2;   // 0..7
    const int tig = lane & 3;    // 0..3

    // ldmatrix lane roles (mapping validated R6/R7)
    const int a_row_off = ((lane >> 3) & 1) * 8 + (lane & 7);
    const int a_kg = lane >> 4;
    const int b_row_off = (lane >> 4) * 8 + (lane & 7);
    const int b_kg = (lane >> 3) & 1;

    auto issue = [&](int chunk, int buf) {
        const int k0 = chunk * 32;
        const uint32_t sA = smem_base + (uint32_t)buf * (STAGE_WORDS * 4);
        const uint32_t sB = sA + 2048 * 4;
#pragma unroll
        for (int l = 0; l < 4; l++) {               // A: 128 rows x 32 halves
            const int idx = tid + l * NTHREADS;
            const int m = idx >> 2, c = idx & 3;
            const uint32_t sw = ((m >> 1) & 3) << 2;
            cp16(sA + (uint32_t)(m * 16 + ((4 * c) ^ sw)) * 4,
                 A + (size_t)(bm + m) * lda + k0 + 8 * c);
        }
#pragma unroll
        for (int l = 0; l < 4; l++) {               // B: 128 rows x 32 halves
            const int idx = tid + l * NTHREADS;
            const int n = idx >> 2, c = idx & 3;
            const uint32_t sw = ((n >> 1) & 3) << 2;
            cp16(sB + (uint32_t)(n * 16 + ((4 * c) ^ sw)) * 4,
                 Bp + (size_t)(bn + n) * ldb + k0 + 8 * c);
        }
    };

    float acc[4][8][4];
#pragma unroll
    for (int i = 0; i < 4; i++)
#pragma unroll
        for (int j = 0; j < 8; j++)
#pragma unroll
            for (int e = 0; e < 4; e++) acc[i][j][e] = 0.0f;

    float rsum[8]; // EPI==3: per-row A sums (rows i*16+gid, i*16+gid+8)
#pragma unroll
    for (int r = 0; r < 8; r++) rsum[r] = 0.0f;

    // Per-lane invariant fragment address pieces: low 16 = row*16, hi = swizzle
    uint32_t aw[4], bw[4];
#pragma unroll
    for (int i = 0; i < 4; i++) {
        const int row = wr * 64 + i * 16 + a_row_off;
        aw[i] = (uint32_t)(row * 16) | (((row >> 1) & 3) << 2) << 16;
    }
#pragma unroll
    for (int jp = 0; jp < 4; jp++) {
        const int row = wc * 64 + jp * 16 + b_row_off;
        bw[jp] = (uint32_t)(row * 16) | (((row >> 1) & 3) << 2) << 16;
    }

    // Prologue (nChunks >= 4 always)
#pragma unroll
    for (int s = 0; s < STAGES - 1; s++) {
        issue(s, s);
        CP_COMMIT();
    }

    int buf = 0;
    for (int t = 0; t < nChunks; t++) {
        CP_WAIT(STAGES - 2);
        __syncthreads();

        const uint32_t sa = smem_base + (uint32_t)buf * (STAGE_WORDS * 4);
        const uint32_t sb = sa + 2048 * 4;

        if (t + STAGES - 1 < nChunks) {
            int pbuf = buf + STAGES - 1;
            if (pbuf >= STAGES) pbuf -= STAGES;
            issue(t + STAGES - 1, pbuf);
        }
        CP_COMMIT();

#pragma unroll
        for (int s = 0; s < 2; s++) { // two K=16 steps per 32-half chunk
            const uint32_t w0 = 8 * s;
            uint32_t af[4][4];
#pragma unroll
            for (int i = 0; i < 4; i++) {
                const uint32_t g = (w0 + 4 * a_kg) ^ (aw[i] >> 16);
                ldsm4(af[i][0], af[i][1], af[i][2], af[i][3],
                      sa + (((aw[i] & 0xffffu) + g) << 2));
            }
            if (EPI == 3) {
                // Row sums of A fragments (P values): rows gid / gid+8 per i.
#pragma unroll
                for (int i = 0; i < 4; i++) {
                    const __half2 h0 = __hadd2(
                        *reinterpret_cast<__half2*>(&af[i][0]),
                        *reinterpret_cast<__half2*>(&af[i][2]));
                    const __half2 h1 = __hadd2(
                        *reinterpret_cast<__half2*>(&af[i][1]),
                        *reinterpret_cast<__half2*>(&af[i][3]));
                    const float2 f0 = __half22float2(h0);
                    const float2 f1 = __half22float2(h1);
                    rsum[2 * i]     += f0.x + f0.y;
                    rsum[2 * i + 1] += f1.x + f1.y;
                }
            }
            uint32_t bf[8][2];
#pragma unroll
            for (int jp = 0; jp < 4; jp++) {
                const uint32_t g = (w0 + 4 * b_kg) ^ (bw[jp] >> 16);
                ldsm4(bf[2 * jp][0], bf[2 * jp][1], bf[2 * jp + 1][0],
                      bf[2 * jp + 1][1],
                      sb + (((bw[jp] & 0xffffu) + g) << 2));
            }
#pragma unroll
            for (int i = 0; i < 4; i++)
#pragma unroll
                for (int j = 0; j < 8; j++) mma_f16(acc[i][j], af[i], bf[j]);
        }
        if (++buf == STAGES) buf = 0;
    }

    if (EPI == 3) {
        // Complete row sums across the 4-lane k-groups (same gid), invert.
#pragma unroll
        for (int r = 0; r < 8; r++) {
            rsum[r] += __shfl_xor_sync(0xffffffffu, rsum[r], 1);
            rsum[r] += __shfl_xor_sync(0xffffffffu, rsum[r], 2);
            rsum[r] = 1.0f / rsum[r];
        }
    }

    if (EPI == 4) {
        // Transpose the CTA tile through smem, write g_vt coalesced.
        CP_WAIT_ALL();
        __syncthreads();
        __half* st = reinterpret_cast<__half*>(sm); // [n:128][m:144 halves]
#pragma unroll
        for (int i = 0; i < 4; i++) {
            const int m = wr * 64 + i * 16 + gid;
#pragma unroll
            for (int j = 0; j < 8; j++) {
                const int col = wc * 64 + j * 8 + 2 * tig;
                st[col * 144 + m]           = __float2half_rn(acc[i][j][0]);
                st[(col + 1) * 144 + m]     = __float2half_rn(acc[i][j][1]);
                st[col * 144 + m + 8]       = __float2half_rn(acc[i][j][2]);
                st[(col + 1) * 144 + m + 8] = __float2half_rn(acc[i][j][3]);
            }
        }
        __syncthreads();
        const int row = tid;        // local n (output d), one row per thread
        const int b = bm >> 11;
        const int t0 = bm & 2047;
        __half* Vt = g_vt + (size_t)b * D * T + (size_t)(bn + row) * T + t0;
#pragma unroll
        for (int c = 0; c < 16; c++) {
            const uint4 v =
                *reinterpret_cast<const uint4*>(st + row * 144 + c * 8);
            *reinterpret_cast<uint4*>(Vt + c * 8) = v;
        }
        return;
    }

    // Epilogue (EPI 1/2/3)
#pragma unroll
    for (int i = 0; i < 4; i++) {
        const int m = bm + wr * 64 + i * 16 + gid;
#pragma unroll
        for (int j = 0; j < 8; j++) {
            const int col = bn + wc * 64 + j * 8 + 2 * tig;
            if (EPI == 1) {
                __half* Ch = (__half*)Cv;
                *reinterpret_cast<__half2*>(Ch + (size_t)m * ldc + col) =
                    __floats2half2_rn(acc[i][j][0], acc[i][j][1]);
                *reinterpret_cast<__half2*>(Ch + (size_t)(m + 8) * ldc + col) =
                    __floats2half2_rn(acc[i][j][2], acc[i][j][3]);
            } else if (EPI == 2) {
                __half* Ch = (__half*)Cv;
                const float e00 = (col     <= m) ? __expf(fmaf(acc[i][j][0], SCALE, -EXPC)) : 0.0f;
                const float e01 = (col + 1 <= m) ? __expf(fmaf(acc[i][j][1], SCALE, -EXPC)) : 0.0f;
                const float e10 = (col     <= m + 8) ? __expf(fmaf(acc[i][j][2], SCALE, -EXPC)) : 0.0f;
                const float e11 = (col + 1 <= m + 8) ? __expf(fmaf(acc[i][j][3], SCALE, -EXPC)) : 0.0f;
                *reinterpret_cast<__half2*>(Ch + (size_t)m * ldc + col) =
                    __floats2half2_rn(e00, e01);
                *reinterpret_cast<__half2*>(Ch + (size_t)(m + 8) * ldc + col) =
                    __floats2half2_rn(e10, e11);
            } else {
                float* Cf = (float*)Cv;
                const float r0 = rsum[2 * i];
                const float r1 = rsum[2 * i + 1];
                *reinterpret_cast<float2*>(Cf + (size_t)m * ldc + col) =
                    make_float2(acc[i][j][0] * r0, acc[i][j][1] * r0);
                *reinterpret_cast<float2*>(Cf + (size_t)(m + 8) * ldc + col) =
                    make_float2(acc[i][j][2] * r1, acc[i][j][3] * r1);
            }
        }
    }
}

// ---------------------------------------------------------------------------
// Kernel 0a: X fp32 -> fp16
// ---------------------------------------------------------------------------
__global__ __launch_bounds__(256) void cvtx_kernel(const float4* __restrict__ src,
                                                   int n4) {
    uint2* dst = reinterpret_cast<uint2*>(g_x);
    const int stride = gridDim.x * blockDim.x;
    for (int i = blockIdx.x * blockDim.x + threadIdx.x; i < n4; i += stride) {
        const float4 v = src[i];
        __half2 h0 = __floats2half2_rn(v.x, v.y);
        __half2 h1 = __floats2half2_rn(v.z, v.w);
        uint2 u;
        u.x = *reinterpret_cast<uint32_t*>(&h0);
        u.y = *reinterpret_cast<uint32_t*>(&h1);
        dst[i] = u;
    }
}

// ---------------------------------------------------------------------------
// Kernel 0b: Wq/Wk fp32 -> fp16 (no transpose), z selects.
// ---------------------------------------------------------------------------
__global__ __launch_bounds__(256) void cvtw_kernel(const float4* __restrict__ Wq,
                                                   const float4* __restrict__ Wk) {
    const float4* src = (blockIdx.z == 0) ? Wq : Wk;
    uint2* dst = reinterpret_cast<uint2*>(g_w16[blockIdx.z]);
    const int n4 = D * D / 4;
    const int stride = gridDim.x * blockDim.x;
    for (int i = blockIdx.x * blockDim.x + threadIdx.x; i < n4; i += stride) {
        const float4 v = src[i];
        __half2 h0 = __floats2half2_rn(v.x, v.y);
        __half2 h1 = __floats2half2_rn(v.z, v.w);
        uint2 u;
        u.x = *reinterpret_cast<uint32_t*>(&h0);
        u.y = *reinterpret_cast<uint32_t*>(&h1);
        dst[i] = u;
    }
}

// ---------------------------------------------------------------------------
// Kernel 0c: Wv fp32 [k][n] -> fp16 Wv^T [n][k], 32x32 smem tiles.
// ---------------------------------------------------------------------------
__global__ __launch_bounds__(256) void wtv_kernel(const float* __restrict__ Wv) {
    __shared__ float tile[32][33];
    const int n0 = blockIdx.x * 32, k0 = blockIdx.y * 32;
    const int c = threadIdx.x & 31, r8 = threadIdx.x >> 5;
#pragma unroll
    for (int r = r8; r < 32; r += 8)
        tile[r][c] = Wv[(size_t)(k0 + r) * D + n0 + c];
    __syncthreads();
#pragma unroll
    for (int r = r8; r < 32; r += 8)
        g_wtv[(size_t)(n0 + r) * D + k0 + c] = __float2half_rn(tile[c][r]);
}

// ---------------------------------------------------------------------------
// Kernel 1: FUSED  Mt = (Wq Wk^T)^T  (64 CTAs, scheduled first)  +
//                  V^T projection   (512 CTAs).
// grid: (8, 72). y<8 -> mt tile; y>=8 -> projv tile (EPI 4).
// ---------------------------------------------------------------------------
__global__ __launch_bounds__(NTHREADS, 2) void mtprojv_kernel() {
    if (blockIdx.y < 8) {
        // Mt[e][d] = sum_i Wk[e][i] * Wq[d][i]
        hgemm<1>(g_w16[1], g_w16[0], g_mt, D, D, D, blockIdx.y * 128,
                 blockIdx.x * 128, D / 32);
    } else {
        // V^T projection with transposed store directly into g_vt.
        hgemm<4>(g_x, g_wtv, nullptr, D, D, 0, (blockIdx.y - 8) * 128,
                 blockIdx.x * 128, D / 32);
    }
}

// ---------------------------------------------------------------------------
// Kernel 2: Y = X @ M  (NT against Mt) -> fp16. Replaces the Q projection;
// the K projection is eliminated entirely (scores = Y X^T).
// ---------------------------------------------------------------------------
__global__ __launch_bounds__(NTHREADS, 2) void projy_kernel() {
    hgemm<1>(g_x, g_mt, g_y, D, D, D, blockIdx.y * 128, blockIdx.x * 128,
             D / 32);
}

// ---------------------------------------------------------------------------
// Kernel 3: unnormalized masked probs P[b] = exp(Y X^T / 32 - 5) (causal).
// B operand is the fp16 input X itself. Skips tiles above the diagonal.
// ---------------------------------------------------------------------------
__global__ __launch_bounds__(NTHREADS, 2) void scores_kernel() {
    const int qm = blockIdx.y;
    const int kn = blockIdx.x;
    if (kn > qm) return;
    const int b = blockIdx.z;
    hgemm<2>(g_y + (size_t)b * T * D, g_x + (size_t)b * T * D,
             g_ph + (size_t)b * T * T, D, D, T, qm * 128, kn * 128, D / 32);
}

// ---------------------------------------------------------------------------
// Kernel 4: O[b] = (P[b] @ V[b]) normalized by inline row sums; k-loop
// truncated at the diagonal. Longest q-blocks launched first.
// ---------------------------------------------------------------------------
__global__ __launch_bounds__(NTHREADS, 2) void pv_kernel(float* __restrict__ O) {
    const int b = blockIdx.z;
    const int qm = (gridDim.y - 1) - blockIdx.y;
    hgemm<3>(g_ph + (size_t)b * T * T, g_vt + (size_t)b * D * T,
             O + (size_t)b * T * D, T, T, D, qm * 128, blockIdx.x * 128,
             (qm + 1) * 4);
}

// ---------------------------------------------------------------------------
extern "C" void kernel_launch(void* const* d_in, const int* in_sizes, int n_in,
                              void* d_out, int out_size) {
    (void)in_sizes; (void)n_in; (void)out_size;
    const float4* X  = (const float4*)d_in[0];
    const float4* Wq = (const float4*)d_in[1];
    const float4* Wk = (const float4*)d_in[2];
    const float*  Wv = (const float*)d_in[3];
    float* O = (float*)d_out;

    cudaFuncSetAttribute(mtprojv_kernel,
                         cudaFuncAttributeMaxDynamicSharedMemorySize,
                         SMEM_BYTES);
    cudaFuncSetAttribute(projy_kernel,
                         cudaFuncAttributeMaxDynamicSharedMemorySize,
                         SMEM_BYTES);
    cudaFuncSetAttribute(scores_kernel,
                         cudaFuncAttributeMaxDynamicSharedMemorySize,
                         SMEM_BYTES);
    cudaFuncSetAttribute(pv_kernel,
                         cudaFuncAttributeMaxDynamicSharedMemorySize,
                         SMEM_BYTES);

    cvtx_kernel<<<1024, 256>>>(X, MPROJ * D / 4);
    cvtw_kernel<<<dim3(256, 1, 2), 256>>>(Wq, Wk);
    wtv_kernel<<<dim3(D / 32, D / 32), 256>>>(Wv);

    mtprojv_kernel<<<dim3(8, 72), NTHREADS, SMEM_BYTES>>>();
    projy_kernel<<<dim3(D / 128, MPROJ / 128), NTHREADS, SMEM_BYTES>>>();
    scores_kernel<<<dim3(T / 128, T / 128, B), NTHREADS, SMEM_BYTES>>>();
    pv_kernel<<<dim3(D / 128, T / 128, B), NTHREADS, SMEM_BYTES>>>(O);
}